// round 6
// baseline (speedup 1.0000x reference)
#include <cuda_runtime.h>
#include <math.h>

#define BB   2
#define SEQ  2048
#define CH   768
#define NH   12
#define HD   64
#define MROWS (BB*SEQ)      // 4096
#define QKVN  (3*CH)        // 2304

// Scratch (device globals: allocation-free rule)
__device__ float g_q[BB*NH*SEQ*HD];
__device__ float g_k[BB*NH*SEQ*HD];
__device__ float g_v[BB*NH*SEQ*HD];
__device__ float g_ctx[MROWS*CH];

// ---------------------------------------------------------------------------
// GEMM core: 128x128 tile, BK=32, 256 threads, 8x8 per-thread register tile.
// Smem layout: row-major [128][32] with XOR granule swizzle so that the
// 16-row-strided fragment loads are bank-conflict-free. A-frag loads are
// warp-broadcast (2 distinct addrs/warp).
// ---------------------------------------------------------------------------

#define GEMM_MAINLOOP(APTR, BPTR, KDIM)                                       \
    float acc[8][8];                                                          \
    _Pragma("unroll")                                                         \
    for (int i = 0; i < 8; i++)                                               \
        _Pragma("unroll")                                                     \
        for (int j = 0; j < 8; j++) acc[i][j] = 0.f;                          \
    for (int k0 = 0; k0 < (KDIM); k0 += 32) {                                 \
        float4 xa[4], wb[4];                                                  \
        _Pragma("unroll")                                                     \
        for (int t = 0; t < 4; t++) {                                         \
            int f = tid + t * 256;                                            \
            int r = f >> 3, g = f & 7;                                        \
            xa[t] = *(const float4*)&(APTR)[(m0 + r) * (KDIM) + k0 + g * 4];  \
            wb[t] = *(const float4*)&(BPTR)[(c0 + r) * (KDIM) + k0 + g * 4];  \
        }                                                                     \
        __syncthreads();                                                      \
        _Pragma("unroll")                                                     \
        for (int t = 0; t < 4; t++) {                                         \
            int f = tid + t * 256;                                            \
            int r = f >> 3, g = f & 7;                                        \
            int sg = g ^ ((r >> 3) & 7);                                      \
            *(float4*)&As[r * 32 + sg * 4] = xa[t];                           \
            *(float4*)&Bs[r * 32 + sg * 4] = wb[t];                           \
        }                                                                     \
        __syncthreads();                                                      \
        _Pragma("unroll")                                                     \
        for (int G = 0; G < 8; G++) {                                         \
            float4 bf[8];                                                     \
            _Pragma("unroll")                                                 \
            for (int jj = 0; jj < 8; jj++)                                    \
                bf[jj] = *(const float4*)&Bs[(tx * 8 + jj) * 32 +             \
                                             ((G ^ (tx & 7)) << 2)];          \
            _Pragma("unroll")                                                 \
            for (int i = 0; i < 8; i++) {                                     \
                float4 a = *(const float4*)&As[(ty * 8 + i) * 32 +            \
                                               ((G ^ (ty & 7)) << 2)];        \
                _Pragma("unroll")                                             \
                for (int jj = 0; jj < 8; jj++) {                              \
                    acc[i][jj] = fmaf(a.x, bf[jj].x, acc[i][jj]);             \
                    acc[i][jj] = fmaf(a.y, bf[jj].y, acc[i][jj]);             \
                    acc[i][jj] = fmaf(a.z, bf[jj].z, acc[i][jj]);             \
                    acc[i][jj] = fmaf(a.w, bf[jj].w, acc[i][jj]);             \
                }                                                             \
            }                                                                 \
        }                                                                     \
    }

// ---------------------------------------------------------------------------
// QKV GEMM: y[m,c] = sum_k x[m,k]*w_qkv[c,k]; epilogue fuses scale + RoPE
// and scatters into head-major q/k/v. Thread owns 8 consecutive cols = 4
// complete rotation pairs (never crosses threads).
// ---------------------------------------------------------------------------
__global__ __launch_bounds__(256, 2) void qkv_gemm_kernel(
    const float* __restrict__ X, const float* __restrict__ W)
{
    __shared__ float As[128 * 32];
    __shared__ float Bs[128 * 32];
    const int tid = threadIdx.x;
    const int tx = tid & 15, ty = tid >> 4;
    const int m0 = blockIdx.y * 128, c0 = blockIdx.x * 128;

    GEMM_MAINLOOP(X, W, CH)

    const int cc    = c0 + tx * 8;
    const int which = cc / CH;            // 0=q, 1=k, 2=v
    const int h     = (cc % CH) / HD;
    const int dd    = cc % HD;            // multiple of 8
    float* dst = (which == 0) ? g_q : (which == 1) ? g_k : g_v;
    const float sc = (which == 0) ? 0.125f : 1.0f;   // 64^-0.5

    float invf[4];
#pragma unroll
    for (int p = 0; p < 4; p++)
        invf[p] = powf(10000.f, -((float)(dd + 2 * p)) / 64.f);

#pragma unroll
    for (int i = 0; i < 8; i++) {
        int m = m0 + ty * 8 + i;
        int b = m / SEQ, n = m % SEQ;
        float out[8];
        if (which == 2) {
#pragma unroll
            for (int j = 0; j < 8; j++) out[j] = acc[i][j];
        } else {
            float fn = (float)n;
#pragma unroll
            for (int p = 0; p < 4; p++) {
                float s, c;
                sincosf(fn * invf[p], &s, &c);
                float x0 = acc[i][2 * p]     * sc;
                float x1 = acc[i][2 * p + 1] * sc;
                out[2 * p]     = x0 * c - x1 * s;
                out[2 * p + 1] = x1 * c + x0 * s;
            }
        }
        float* base = &dst[((b * NH + h) * SEQ + n) * HD + dd];
        *(float4*)base       = make_float4(out[0], out[1], out[2], out[3]);
        *(float4*)(base + 4) = make_float4(out[4], out[5], out[6], out[7]);
    }
}

// ---------------------------------------------------------------------------
// Flash attention: block = (b*h, 128-query tile), 256 threads, 8x4 per-thread
// S tile. K stored with XOR granule swizzle for conflict-free strided loads.
// Online softmax row stats in registers; P staged via smem for P.V.
// ---------------------------------------------------------------------------
__global__ __launch_bounds__(256, 2) void flash_kernel()
{
    extern __shared__ float sm[];
    float* Qs = sm;                    // [128][64]
    float* Ks = sm + 128 * 64;         // [64][64] swizzled
    float* Vs = sm + 128 * 64 + 64 * 64;
    float* Ps = sm + 128 * 64 + 2 * 64 * 64;   // [128][64]

    const int tid = threadIdx.x;
    const int tx = tid & 15, ty = tid >> 4;
    const int bh = blockIdx.y;
    const int q0 = blockIdx.x * 128;

    const float* qb = g_q + (bh * SEQ + q0) * HD;
    const float* kb = g_k + bh * SEQ * HD;
    const float* vb = g_v + bh * SEQ * HD;

    // load Q tile (linear layout)
#pragma unroll
    for (int t = 0; t < 8; t++) {
        int f = tid + t * 256;
        int r = f >> 4, c4 = f & 15;
        *(float4*)&Qs[r * 64 + c4 * 4] = *(const float4*)&qb[r * HD + c4 * 4];
    }

    float mi[8], li[8], o[8][4];
#pragma unroll
    for (int i = 0; i < 8; i++) {
        mi[i] = -1e30f; li[i] = 0.f;
#pragma unroll
        for (int j = 0; j < 4; j++) o[i][j] = 0.f;
    }

    for (int j0 = 0; j0 < SEQ; j0 += 64) {
        __syncthreads();   // previous tile's Ps/Vs readers done
#pragma unroll
        for (int t = 0; t < 4; t++) {
            int f = tid + t * 256;
            int r = f >> 4, c4 = f & 15;
            // K swizzled, V linear
            *(float4*)&Ks[r * 64 + ((c4 ^ ((r >> 2) & 15)) << 2)] =
                *(const float4*)&kb[(j0 + r) * HD + c4 * 4];
            *(float4*)&Vs[r * 64 + c4 * 4] =
                *(const float4*)&vb[(j0 + r) * HD + c4 * 4];
        }
        __syncthreads();

        // S = Q . K^T : 8x4 per thread, vectorized over k (granules of 4)
        float s[8][4];
#pragma unroll
        for (int i = 0; i < 8; i++)
#pragma unroll
            for (int j = 0; j < 4; j++) s[i][j] = 0.f;

#pragma unroll
        for (int G = 0; G < 16; G++) {
            float4 bf[4];
#pragma unroll
            for (int j = 0; j < 4; j++)
                bf[j] = *(const float4*)&Ks[(tx * 4 + j) * 64 + ((G ^ tx) << 2)];
#pragma unroll
            for (int i = 0; i < 8; i++) {
                float4 a = *(const float4*)&Qs[(ty * 8 + i) * 64 + (G << 2)];
#pragma unroll
                for (int j = 0; j < 4; j++) {
                    s[i][j] = fmaf(a.x, bf[j].x, s[i][j]);
                    s[i][j] = fmaf(a.y, bf[j].y, s[i][j]);
                    s[i][j] = fmaf(a.z, bf[j].z, s[i][j]);
                    s[i][j] = fmaf(a.w, bf[j].w, s[i][j]);
                }
            }
        }

        // online softmax (row reductions over the 16-lane tx group)
#pragma unroll
        for (int i = 0; i < 8; i++) {
            float mx = fmaxf(fmaxf(s[i][0], s[i][1]), fmaxf(s[i][2], s[i][3]));
#pragma unroll
            for (int msk = 8; msk; msk >>= 1)
                mx = fmaxf(mx, __shfl_xor_sync(0xffffffffu, mx, msk));
            float mnew = fmaxf(mi[i], mx);
            float4 p;
            p.x = __expf(s[i][0] - mnew);
            p.y = __expf(s[i][1] - mnew);
            p.z = __expf(s[i][2] - mnew);
            p.w = __expf(s[i][3] - mnew);
            float sum = p.x + p.y + p.z + p.w;
#pragma unroll
            for (int msk = 8; msk; msk >>= 1)
                sum += __shfl_xor_sync(0xffffffffu, sum, msk);
            float alpha = __expf(mi[i] - mnew);
            li[i] = li[i] * alpha + sum;
            mi[i] = mnew;
            o[i][0] *= alpha; o[i][1] *= alpha;
            o[i][2] *= alpha; o[i][3] *= alpha;
            *(float4*)&Ps[(ty * 8 + i) * 64 + tx * 4] = p;
        }
        __syncthreads();

        // O += P . V  (vectorized over j, granules of 4)
#pragma unroll
        for (int J = 0; J < 16; J++) {
            float4 v0 = *(const float4*)&Vs[(J * 4 + 0) * 64 + tx * 4];
            float4 v1 = *(const float4*)&Vs[(J * 4 + 1) * 64 + tx * 4];
            float4 v2 = *(const float4*)&Vs[(J * 4 + 2) * 64 + tx * 4];
            float4 v3 = *(const float4*)&Vs[(J * 4 + 3) * 64 + tx * 4];
#pragma unroll
            for (int i = 0; i < 8; i++) {
                float4 p = *(const float4*)&Ps[(ty * 8 + i) * 64 + (J << 2)];
                o[i][0] = fmaf(p.x, v0.x, o[i][0]);
                o[i][1] = fmaf(p.x, v0.y, o[i][1]);
                o[i][2] = fmaf(p.x, v0.z, o[i][2]);
                o[i][3] = fmaf(p.x, v0.w, o[i][3]);
                o[i][0] = fmaf(p.y, v1.x, o[i][0]);
                o[i][1] = fmaf(p.y, v1.y, o[i][1]);
                o[i][2] = fmaf(p.y, v1.z, o[i][2]);
                o[i][3] = fmaf(p.y, v1.w, o[i][3]);
                o[i][0] = fmaf(p.z, v2.x, o[i][0]);
                o[i][1] = fmaf(p.z, v2.y, o[i][1]);
                o[i][2] = fmaf(p.z, v2.z, o[i][2]);
                o[i][3] = fmaf(p.z, v2.w, o[i][3]);
                o[i][0] = fmaf(p.w, v3.x, o[i][0]);
                o[i][1] = fmaf(p.w, v3.y, o[i][1]);
                o[i][2] = fmaf(p.w, v3.z, o[i][2]);
                o[i][3] = fmaf(p.w, v3.w, o[i][3]);
            }
        }
    }

    // write ctx in [B,N,C] token-major layout
    const int b = bh / NH, h = bh % NH;
#pragma unroll
    for (int i = 0; i < 8; i++) {
        int n = q0 + ty * 8 + i;
        float inv = 1.f / li[i];
        float4 r = make_float4(o[i][0] * inv, o[i][1] * inv,
                               o[i][2] * inv, o[i][3] * inv);
        *(float4*)&g_ctx[(b * SEQ + n) * CH + h * HD + tx * 4] = r;
    }
}

// ---------------------------------------------------------------------------
// Output projection: out[m,c] = sum_k ctx[m,k]*w_proj[c,k] + b_proj[c]
// ---------------------------------------------------------------------------
__global__ __launch_bounds__(256, 2) void proj_gemm_kernel(
    const float* __restrict__ W, const float* __restrict__ bias,
    float* __restrict__ out)
{
    __shared__ float As[128 * 32];
    __shared__ float Bs[128 * 32];
    const int tid = threadIdx.x;
    const int tx = tid & 15, ty = tid >> 4;
    const int m0 = blockIdx.y * 128, c0 = blockIdx.x * 128;

    GEMM_MAINLOOP(g_ctx, W, CH)

    const int c = c0 + tx * 8;
    float4 bv0 = *(const float4*)&bias[c];
    float4 bv1 = *(const float4*)&bias[c + 4];
#pragma unroll
    for (int i = 0; i < 8; i++) {
        int m = m0 + ty * 8 + i;
        float4 r0 = make_float4(acc[i][0] + bv0.x, acc[i][1] + bv0.y,
                                acc[i][2] + bv0.z, acc[i][3] + bv0.w);
        float4 r1 = make_float4(acc[i][4] + bv1.x, acc[i][5] + bv1.y,
                                acc[i][6] + bv1.z, acc[i][7] + bv1.w);
        *(float4*)&out[m * CH + c]     = r0;
        *(float4*)&out[m * CH + c + 4] = r1;
    }
}

// ---------------------------------------------------------------------------
extern "C" void kernel_launch(void* const* d_in, const int* in_sizes, int n_in,
                              void* d_out, int out_size)
{
    const float* x      = (const float*)d_in[0];
    const float* w_qkv  = (const float*)d_in[1];
    const float* w_proj = (const float*)d_in[2];
    const float* b_proj = (const float*)d_in[3];
    float* out = (float*)d_out;

    const int flash_smem = (128*64 + 64*64 + 64*64 + 128*64) * (int)sizeof(float); // 98304 B
    cudaFuncSetAttribute(flash_kernel,
                         cudaFuncAttributeMaxDynamicSharedMemorySize, flash_smem);

    dim3 g1(QKVN / 128, MROWS / 128);   // 18 x 32
    qkv_gemm_kernel<<<g1, 256>>>(x, w_qkv);

    dim3 g2(SEQ / 128, BB * NH);        // 16 x 24
    flash_kernel<<<g2, 256, flash_smem>>>();

    dim3 g3(CH / 128, MROWS / 128);     // 6 x 32
    proj_gemm_kernel<<<g3, 256>>>(w_proj, b_proj, out);
}

// round 8
// speedup vs baseline: 1.3170x; 1.3170x over previous
#include <cuda_runtime.h>
#include <cuda_bf16.h>
#include <math.h>
#include <stdint.h>

#define BB   2
#define SEQ  2048
#define CH   768
#define NH   12
#define HD   64
#define MROWS (BB*SEQ)      // 4096
#define QKVN  (3*CH)        // 2304
#define SSTR  40            // smem bf16 stride: conflict-free fragment loads

// Scratch (device globals: allocation-free rule)
__device__ __align__(16) float g_q[BB*NH*SEQ*HD];
__device__ __align__(16) float g_k[BB*NH*SEQ*HD];
__device__ __align__(16) float g_v[BB*NH*SEQ*HD];
__device__ __align__(16) float g_ctx[MROWS*CH];

// ===========================================================================
// mma.sync m16n8k16 bf16 (portable sm_80+ encoding; runs on tensor pipe)
// ===========================================================================
__device__ __forceinline__ void mma16816(float* c, const uint32_t* a,
                                         const uint32_t* b) {
    asm volatile(
        "mma.sync.aligned.m16n8k16.row.col.f32.bf16.bf16.f32 "
        "{%0,%1,%2,%3}, {%4,%5,%6,%7}, {%8,%9}, {%0,%1,%2,%3};"
        : "+f"(c[0]), "+f"(c[1]), "+f"(c[2]), "+f"(c[3])
        : "r"(a[0]), "r"(a[1]), "r"(a[2]), "r"(a[3]), "r"(b[0]), "r"(b[1]));
}

// A fragment: 16x16 tile at (row0, k0). regs: a0=(g,kl) a1=(g+8,kl) a2=(g,kl+8) a3=(g+8,kl+8)
__device__ __forceinline__ void lda(uint32_t a[4], const __nv_bfloat16* S,
                                    int row0, int k0, int lane) {
    const int g = lane >> 2, t2 = (lane & 3) * 2;
    a[0] = *(const uint32_t*)&S[(row0 + g)     * SSTR + k0 + t2];
    a[1] = *(const uint32_t*)&S[(row0 + g + 8) * SSTR + k0 + t2];
    a[2] = *(const uint32_t*)&S[(row0 + g)     * SSTR + k0 + t2 + 8];
    a[3] = *(const uint32_t*)&S[(row0 + g + 8) * SSTR + k0 + t2 + 8];
}
// B fragment (col-major 16x8 = our [n][k] smem): b0=(col g, k t2) b1=(col g, k t2+8)
__device__ __forceinline__ void ldb(uint32_t b[2], const __nv_bfloat16* S,
                                    int col0, int k0, int lane) {
    const int g = lane >> 2, t2 = (lane & 3) * 2;
    b[0] = *(const uint32_t*)&S[(col0 + g) * SSTR + k0 + t2];
    b[1] = *(const uint32_t*)&S[(col0 + g) * SSTR + k0 + t2 + 8];
}

// fp32 -> bf16 hi/lo split, packed as 2x uint2 (4 bf16 each)
__device__ __forceinline__ void split4(float4 v, uint2& hi, uint2& lo) {
    __nv_bfloat16 hx = __float2bfloat16_rn(v.x), hy = __float2bfloat16_rn(v.y),
                  hz = __float2bfloat16_rn(v.z), hw = __float2bfloat16_rn(v.w);
    __nv_bfloat16 lx = __float2bfloat16_rn(v.x - __bfloat162float(hx)),
                  ly = __float2bfloat16_rn(v.y - __bfloat162float(hy)),
                  lz = __float2bfloat16_rn(v.z - __bfloat162float(hz)),
                  lw = __float2bfloat16_rn(v.w - __bfloat162float(hw));
    __nv_bfloat162 h01 = __halves2bfloat162(hx, hy), h23 = __halves2bfloat162(hz, hw);
    __nv_bfloat162 l01 = __halves2bfloat162(lx, ly), l23 = __halves2bfloat162(lz, lw);
    hi = make_uint2(*(uint32_t*)&h01, *(uint32_t*)&h23);
    lo = make_uint2(*(uint32_t*)&l01, *(uint32_t*)&l23);
}

// ---------------------------------------------------------------------------
// GEMM core: D[128,128] = A[m0:+128, :K] . B[c0:+128, :K]^T via mma.sync,
// bf16 hi/lo split (terms hh + hl + lh), fp32 accum. 256 threads / 8 warps.
// acc[mf][nf][4] left in registers for caller's epilogue.
// ---------------------------------------------------------------------------
__device__ __forceinline__ void gemm_mma(
    const float* __restrict__ A, const float* __restrict__ B, int K,
    int m0, int c0,
    __nv_bfloat16* sAh, __nv_bfloat16* sAl,
    __nv_bfloat16* sBh, __nv_bfloat16* sBl,
    float acc[4][4][4])
{
    const int tid = threadIdx.x, lane = tid & 31, wid = tid >> 5;
    const int wm = (wid >> 2) * 64, wn = (wid & 3) * 32;

#pragma unroll
    for (int i = 0; i < 4; i++)
#pragma unroll
        for (int j = 0; j < 4; j++)
#pragma unroll
            for (int r = 0; r < 4; r++) acc[i][j][r] = 0.f;

    float4 pa[4], pb[4];
    // prefetch chunk 0
#pragma unroll
    for (int t = 0; t < 4; t++) {
        int f = tid + t * 256, r = f >> 3, g = f & 7;
        pa[t] = *(const float4*)&A[(size_t)(m0 + r) * K + g * 4];
        pb[t] = *(const float4*)&B[(size_t)(c0 + r) * K + g * 4];
    }

    const int nck = K / 32;
    for (int ck = 0; ck < nck; ck++) {
        // publish current chunk to smem (hi/lo split)
#pragma unroll
        for (int t = 0; t < 4; t++) {
            int f = tid + t * 256, r = f >> 3, g = f & 7;
            uint2 hi, lo;
            split4(pa[t], hi, lo);
            *(uint2*)&sAh[r * SSTR + g * 4] = hi;
            *(uint2*)&sAl[r * SSTR + g * 4] = lo;
            split4(pb[t], hi, lo);
            *(uint2*)&sBh[r * SSTR + g * 4] = hi;
            *(uint2*)&sBl[r * SSTR + g * 4] = lo;
        }
        __syncthreads();

        // prefetch next chunk (LDG latency hidden under MMA below)
        if (ck + 1 < nck) {
            const int k0 = (ck + 1) * 32;
#pragma unroll
            for (int t = 0; t < 4; t++) {
                int f = tid + t * 256, r = f >> 3, g = f & 7;
                pa[t] = *(const float4*)&A[(size_t)(m0 + r) * K + k0 + g * 4];
                pb[t] = *(const float4*)&B[(size_t)(c0 + r) * K + k0 + g * 4];
            }
        }

#pragma unroll
        for (int ks = 0; ks < 32; ks += 16) {
            uint32_t af[4][4];
            // hi(A) x {hi(B), lo(B)}
#pragma unroll
            for (int mf = 0; mf < 4; mf++) lda(af[mf], sAh, wm + mf * 16, ks, lane);
#pragma unroll
            for (int nf = 0; nf < 4; nf++) {
                uint32_t bh[2], bl[2];
                ldb(bh, sBh, wn + nf * 8, ks, lane);
                ldb(bl, sBl, wn + nf * 8, ks, lane);
#pragma unroll
                for (int mf = 0; mf < 4; mf++) {
                    mma16816(acc[mf][nf], af[mf], bh);
                    mma16816(acc[mf][nf], af[mf], bl);
                }
            }
            // lo(A) x hi(B)
#pragma unroll
            for (int mf = 0; mf < 4; mf++) lda(af[mf], sAl, wm + mf * 16, ks, lane);
#pragma unroll
            for (int nf = 0; nf < 4; nf++) {
                uint32_t bh[2];
                ldb(bh, sBh, wn + nf * 8, ks, lane);
#pragma unroll
                for (int mf = 0; mf < 4; mf++)
                    mma16816(acc[mf][nf], af[mf], bh);
            }
        }
        __syncthreads();
    }
}

// ---------------------------------------------------------------------------
// QKV GEMM + fused scale/RoPE epilogue -> head-major q/k/v.
// C-fragment cols come in (even, even+1) pairs = exactly one RoPE pair.
// ---------------------------------------------------------------------------
__global__ __launch_bounds__(256, 2) void qkv_mma_kernel(
    const float* __restrict__ X, const float* __restrict__ W)
{
    __shared__ __nv_bfloat16 sAh[128 * SSTR], sAl[128 * SSTR];
    __shared__ __nv_bfloat16 sBh[128 * SSTR], sBl[128 * SSTR];
    const int m0 = blockIdx.y * 128, c0 = blockIdx.x * 128;
    float acc[4][4][4];
    gemm_mma(X, W, CH, m0, c0, sAh, sAl, sBh, sBl, acc);

    const int tid = threadIdx.x, lane = tid & 31, wid = tid >> 5;
    const int wm = (wid >> 2) * 64, wn = (wid & 3) * 32;
    const int g = lane >> 2, t2 = (lane & 3) * 2;

    const int which = (c0 + wn) / CH;    // block's 128 cols stay in one of q/k/v
    float* dstp = (which == 0) ? g_q : (which == 1) ? g_k : g_v;
    const float sc = (which == 0) ? 0.125f : 1.0f;

#pragma unroll
    for (int nf = 0; nf < 4; nf++) {
        const int col = c0 + wn + nf * 8 + t2;
        const int h   = (col % CH) >> 6;
        const int dd  = col & 63;                 // even
        const float inv = powf(10000.f, -((float)dd) / 64.f);
#pragma unroll
        for (int mf = 0; mf < 4; mf++) {
#pragma unroll
            for (int rr = 0; rr < 2; rr++) {
                const int m = m0 + wm + mf * 16 + g + rr * 8;
                const int b = m >> 11, n = m & 2047;
                float x0 = acc[mf][nf][rr * 2], x1 = acc[mf][nf][rr * 2 + 1];
                float2 r;
                if (which == 2) {
                    r = make_float2(x0, x1);
                } else {
                    float s, c;
                    sincosf((float)n * inv, &s, &c);
                    x0 *= sc; x1 *= sc;
                    r = make_float2(x0 * c - x1 * s, x1 * c + x0 * s);
                }
                *(float2*)&dstp[(((size_t)b * NH + h) * SEQ + n) * HD + dd] = r;
            }
        }
    }
}

// ---------------------------------------------------------------------------
// Output projection GEMM + bias epilogue.
// ---------------------------------------------------------------------------
__global__ __launch_bounds__(256, 2) void proj_mma_kernel(
    const float* __restrict__ W, const float* __restrict__ bias,
    float* __restrict__ out)
{
    __shared__ __nv_bfloat16 sAh[128 * SSTR], sAl[128 * SSTR];
    __shared__ __nv_bfloat16 sBh[128 * SSTR], sBl[128 * SSTR];
    const int m0 = blockIdx.y * 128, c0 = blockIdx.x * 128;
    float acc[4][4][4];
    gemm_mma(g_ctx, W, CH, m0, c0, sAh, sAl, sBh, sBl, acc);

    const int tid = threadIdx.x, lane = tid & 31, wid = tid >> 5;
    const int wm = (wid >> 2) * 64, wn = (wid & 3) * 32;
    const int g = lane >> 2, t2 = (lane & 3) * 2;

#pragma unroll
    for (int nf = 0; nf < 4; nf++) {
        const int col = c0 + wn + nf * 8 + t2;
        const float2 bv = *(const float2*)&bias[col];
#pragma unroll
        for (int mf = 0; mf < 4; mf++) {
#pragma unroll
            for (int rr = 0; rr < 2; rr++) {
                const int m = m0 + wm + mf * 16 + g + rr * 8;
                *(float2*)&out[(size_t)m * CH + col] =
                    make_float2(acc[mf][nf][rr * 2]     + bv.x,
                                acc[mf][nf][rr * 2 + 1] + bv.y);
            }
        }
    }
}

// ---------------------------------------------------------------------------
// Flash attention: UNCHANGED validated SIMT kernel (R5).
// ---------------------------------------------------------------------------
__global__ __launch_bounds__(256, 2) void flash_kernel()
{
    extern __shared__ float sm[];
    float* Qs = sm;
    float* Ks = sm + 128 * 64;
    float* Vs = sm + 128 * 64 + 64 * 64;
    float* Ps = sm + 128 * 64 + 2 * 64 * 64;

    const int tid = threadIdx.x;
    const int tx = tid & 15, ty = tid >> 4;
    const int bh = blockIdx.y;
    const int q0 = blockIdx.x * 128;

    const float* qb = g_q + (bh * SEQ + q0) * HD;
    const float* kb = g_k + bh * SEQ * HD;
    const float* vb = g_v + bh * SEQ * HD;

#pragma unroll
    for (int t = 0; t < 8; t++) {
        int f = tid + t * 256;
        int r = f >> 4, c4 = f & 15;
        *(float4*)&Qs[r * 64 + c4 * 4] = *(const float4*)&qb[r * HD + c4 * 4];
    }

    float mi[8], li[8], o[8][4];
#pragma unroll
    for (int i = 0; i < 8; i++) {
        mi[i] = -1e30f; li[i] = 0.f;
#pragma unroll
        for (int j = 0; j < 4; j++) o[i][j] = 0.f;
    }

    for (int j0 = 0; j0 < SEQ; j0 += 64) {
        __syncthreads();
#pragma unroll
        for (int t = 0; t < 4; t++) {
            int f = tid + t * 256;
            int r = f >> 4, c4 = f & 15;
            *(float4*)&Ks[r * 64 + ((c4 ^ ((r >> 2) & 15)) << 2)] =
                *(const float4*)&kb[(j0 + r) * HD + c4 * 4];
            *(float4*)&Vs[r * 64 + c4 * 4] =
                *(const float4*)&vb[(j0 + r) * HD + c4 * 4];
        }
        __syncthreads();

        float s[8][4];
#pragma unroll
        for (int i = 0; i < 8; i++)
#pragma unroll
            for (int j = 0; j < 4; j++) s[i][j] = 0.f;

#pragma unroll
        for (int G = 0; G < 16; G++) {
            float4 bf[4];
#pragma unroll
            for (int j = 0; j < 4; j++)
                bf[j] = *(const float4*)&Ks[(tx * 4 + j) * 64 + ((G ^ tx) << 2)];
#pragma unroll
            for (int i = 0; i < 8; i++) {
                float4 a = *(const float4*)&Qs[(ty * 8 + i) * 64 + (G << 2)];
#pragma unroll
                for (int j = 0; j < 4; j++) {
                    s[i][j] = fmaf(a.x, bf[j].x, s[i][j]);
                    s[i][j] = fmaf(a.y, bf[j].y, s[i][j]);
                    s[i][j] = fmaf(a.z, bf[j].z, s[i][j]);
                    s[i][j] = fmaf(a.w, bf[j].w, s[i][j]);
                }
            }
        }

#pragma unroll
        for (int i = 0; i < 8; i++) {
            float mx = fmaxf(fmaxf(s[i][0], s[i][1]), fmaxf(s[i][2], s[i][3]));
#pragma unroll
            for (int msk = 8; msk; msk >>= 1)
                mx = fmaxf(mx, __shfl_xor_sync(0xffffffffu, mx, msk));
            float mnew = fmaxf(mi[i], mx);
            float4 p;
            p.x = __expf(s[i][0] - mnew);
            p.y = __expf(s[i][1] - mnew);
            p.z = __expf(s[i][2] - mnew);
            p.w = __expf(s[i][3] - mnew);
            float sum = p.x + p.y + p.z + p.w;
#pragma unroll
            for (int msk = 8; msk; msk >>= 1)
                sum += __shfl_xor_sync(0xffffffffu, sum, msk);
            float alpha = __expf(mi[i] - mnew);
            li[i] = li[i] * alpha + sum;
            mi[i] = mnew;
            o[i][0] *= alpha; o[i][1] *= alpha;
            o[i][2] *= alpha; o[i][3] *= alpha;
            *(float4*)&Ps[(ty * 8 + i) * 64 + tx * 4] = p;
        }
        __syncthreads();

#pragma unroll
        for (int J = 0; J < 16; J++) {
            float4 v0 = *(const float4*)&Vs[(J * 4 + 0) * 64 + tx * 4];
            float4 v1 = *(const float4*)&Vs[(J * 4 + 1) * 64 + tx * 4];
            float4 v2 = *(const float4*)&Vs[(J * 4 + 2) * 64 + tx * 4];
            float4 v3 = *(const float4*)&Vs[(J * 4 + 3) * 64 + tx * 4];
#pragma unroll
            for (int i = 0; i < 8; i++) {
                float4 p = *(const float4*)&Ps[(ty * 8 + i) * 64 + (J << 2)];
                o[i][0] = fmaf(p.x, v0.x, o[i][0]);
                o[i][1] = fmaf(p.x, v0.y, o[i][1]);
                o[i][2] = fmaf(p.x, v0.z, o[i][2]);
                o[i][3] = fmaf(p.x, v0.w, o[i][3]);
                o[i][0] = fmaf(p.y, v1.x, o[i][0]);
                o[i][1] = fmaf(p.y, v1.y, o[i][1]);
                o[i][2] = fmaf(p.y, v1.z, o[i][2]);
                o[i][3] = fmaf(p.y, v1.w, o[i][3]);
                o[i][0] = fmaf(p.z, v2.x, o[i][0]);
                o[i][1] = fmaf(p.z, v2.y, o[i][1]);
                o[i][2] = fmaf(p.z, v2.z, o[i][2]);
                o[i][3] = fmaf(p.z, v2.w, o[i][3]);
                o[i][0] = fmaf(p.w, v3.x, o[i][0]);
                o[i][1] = fmaf(p.w, v3.y, o[i][1]);
                o[i][2] = fmaf(p.w, v3.z, o[i][2]);
                o[i][3] = fmaf(p.w, v3.w, o[i][3]);
            }
        }
    }

    const int b = bh / NH, h = bh % NH;
#pragma unroll
    for (int i = 0; i < 8; i++) {
        int n = q0 + ty * 8 + i;
        float inv = 1.f / li[i];
        float4 r = make_float4(o[i][0] * inv, o[i][1] * inv,
                               o[i][2] * inv, o[i][3] * inv);
        *(float4*)&g_ctx[(b * SEQ + n) * CH + h * HD + tx * 4] = r;
    }
}

// ---------------------------------------------------------------------------
extern "C" void kernel_launch(void* const* d_in, const int* in_sizes, int n_in,
                              void* d_out, int out_size)
{
    const float* x      = (const float*)d_in[0];
    const float* w_qkv  = (const float*)d_in[1];
    const float* w_proj = (const float*)d_in[2];
    const float* b_proj = (const float*)d_in[3];
    float* out = (float*)d_out;

    const int flash_smem = (128*64 + 64*64 + 64*64 + 128*64) * (int)sizeof(float);
    cudaFuncSetAttribute(flash_kernel,
                         cudaFuncAttributeMaxDynamicSharedMemorySize, flash_smem);

    dim3 g1(QKVN / 128, MROWS / 128);   // 18 x 32
    qkv_mma_kernel<<<g1, 256>>>(x, w_qkv);

    dim3 g2(SEQ / 128, BB * NH);        // 16 x 24
    flash_kernel<<<g2, 256, flash_smem>>>();

    dim3 g3(CH / 128, MROWS / 128);     // 6 x 32
    proj_mma_kernel<<<g3, 256>>>(w_proj, b_proj, out);
}

// round 9
// speedup vs baseline: 2.3746x; 1.8031x over previous
#include <cuda_runtime.h>
#include <cuda_bf16.h>
#include <math.h>
#include <stdint.h>

#define BB   2
#define SEQ  2048
#define CH   768
#define NH   12
#define HD   64
#define MROWS (BB*SEQ)      // 4096
#define QKVN  (3*CH)        // 2304
#define SSTR  40            // gemm smem stride (bf16)
#define KSTR  72            // flash smem stride (bf16), 64+8: conflict-free

// Scratch (device globals)
__device__ __align__(16) __nv_bfloat16 g_qh[BB*NH*SEQ*HD], g_ql[BB*NH*SEQ*HD];
__device__ __align__(16) __nv_bfloat16 g_kh[BB*NH*SEQ*HD], g_kl[BB*NH*SEQ*HD];
__device__ __align__(16) __nv_bfloat16 g_vth[BB*NH*HD*SEQ], g_vtl[BB*NH*HD*SEQ]; // [bh][d][n]
__device__ __align__(16) float g_ctx[MROWS*CH];

// ===========================================================================
// mma.sync m16n8k16 bf16 helpers
// ===========================================================================
__device__ __forceinline__ void mma16816(float* c, const uint32_t* a,
                                         const uint32_t* b) {
    asm volatile(
        "mma.sync.aligned.m16n8k16.row.col.f32.bf16.bf16.f32 "
        "{%0,%1,%2,%3}, {%4,%5,%6,%7}, {%8,%9}, {%0,%1,%2,%3};"
        : "+f"(c[0]), "+f"(c[1]), "+f"(c[2]), "+f"(c[3])
        : "r"(a[0]), "r"(a[1]), "r"(a[2]), "r"(a[3]), "r"(b[0]), "r"(b[1]));
}
__device__ __forceinline__ void lda(uint32_t a[4], const __nv_bfloat16* S,
                                    int row0, int k0, int lane) {
    const int g = lane >> 2, t2 = (lane & 3) * 2;
    a[0] = *(const uint32_t*)&S[(row0 + g)     * SSTR + k0 + t2];
    a[1] = *(const uint32_t*)&S[(row0 + g + 8) * SSTR + k0 + t2];
    a[2] = *(const uint32_t*)&S[(row0 + g)     * SSTR + k0 + t2 + 8];
    a[3] = *(const uint32_t*)&S[(row0 + g + 8) * SSTR + k0 + t2 + 8];
}
__device__ __forceinline__ void ldb(uint32_t b[2], const __nv_bfloat16* S,
                                    int col0, int k0, int lane) {
    const int g = lane >> 2, t2 = (lane & 3) * 2;
    b[0] = *(const uint32_t*)&S[(col0 + g) * SSTR + k0 + t2];
    b[1] = *(const uint32_t*)&S[(col0 + g) * SSTR + k0 + t2 + 8];
}
// flash variant with KSTR
__device__ __forceinline__ void ldbf(uint32_t b[2], const __nv_bfloat16* S,
                                     int col0, int k0, int lane) {
    const int g = lane >> 2, t2 = (lane & 3) * 2;
    b[0] = *(const uint32_t*)&S[(col0 + g) * KSTR + k0 + t2];
    b[1] = *(const uint32_t*)&S[(col0 + g) * KSTR + k0 + t2 + 8];
}

__device__ __forceinline__ void splitpair(float x, float y,
                                          uint32_t& hi, uint32_t& lo) {
    __nv_bfloat16 hx = __float2bfloat16_rn(x), hy = __float2bfloat16_rn(y);
    __nv_bfloat162 h = __halves2bfloat162(hx, hy);
    hi = *(uint32_t*)&h;
    __nv_bfloat162 l = __floats2bfloat162_rn(x - __bfloat162float(hx),
                                             y - __bfloat162float(hy));
    lo = *(uint32_t*)&l;
}
__device__ __forceinline__ void split4(float4 v, uint2& hi, uint2& lo) {
    splitpair(v.x, v.y, hi.x, lo.x);
    splitpair(v.z, v.w, hi.y, lo.y);
}

// ---------------------------------------------------------------------------
// GEMM core (unchanged from R8): D[128,128]=A.B^T, hi/lo split, 8 warps.
// ---------------------------------------------------------------------------
__device__ __forceinline__ void gemm_mma(
    const float* __restrict__ A, const float* __restrict__ B, int K,
    int m0, int c0,
    __nv_bfloat16* sAh, __nv_bfloat16* sAl,
    __nv_bfloat16* sBh, __nv_bfloat16* sBl,
    float acc[4][4][4])
{
    const int tid = threadIdx.x, lane = tid & 31, wid = tid >> 5;
    const int wm = (wid >> 2) * 64, wn = (wid & 3) * 32;

#pragma unroll
    for (int i = 0; i < 4; i++)
#pragma unroll
        for (int j = 0; j < 4; j++)
#pragma unroll
            for (int r = 0; r < 4; r++) acc[i][j][r] = 0.f;

    float4 pa[4], pb[4];
#pragma unroll
    for (int t = 0; t < 4; t++) {
        int f = tid + t * 256, r = f >> 3, g = f & 7;
        pa[t] = *(const float4*)&A[(size_t)(m0 + r) * K + g * 4];
        pb[t] = *(const float4*)&B[(size_t)(c0 + r) * K + g * 4];
    }

    const int nck = K / 32;
    for (int ck = 0; ck < nck; ck++) {
#pragma unroll
        for (int t = 0; t < 4; t++) {
            int f = tid + t * 256, r = f >> 3, g = f & 7;
            uint2 hi, lo;
            split4(pa[t], hi, lo);
            *(uint2*)&sAh[r * SSTR + g * 4] = hi;
            *(uint2*)&sAl[r * SSTR + g * 4] = lo;
            split4(pb[t], hi, lo);
            *(uint2*)&sBh[r * SSTR + g * 4] = hi;
            *(uint2*)&sBl[r * SSTR + g * 4] = lo;
        }
        __syncthreads();
        if (ck + 1 < nck) {
            const int k0 = (ck + 1) * 32;
#pragma unroll
            for (int t = 0; t < 4; t++) {
                int f = tid + t * 256, r = f >> 3, g = f & 7;
                pa[t] = *(const float4*)&A[(size_t)(m0 + r) * K + k0 + g * 4];
                pb[t] = *(const float4*)&B[(size_t)(c0 + r) * K + k0 + g * 4];
            }
        }
#pragma unroll
        for (int ks = 0; ks < 32; ks += 16) {
            uint32_t af[4][4];
#pragma unroll
            for (int mf = 0; mf < 4; mf++) lda(af[mf], sAh, wm + mf * 16, ks, lane);
#pragma unroll
            for (int nf = 0; nf < 4; nf++) {
                uint32_t bh[2], bl[2];
                ldb(bh, sBh, wn + nf * 8, ks, lane);
                ldb(bl, sBl, wn + nf * 8, ks, lane);
#pragma unroll
                for (int mf = 0; mf < 4; mf++) {
                    mma16816(acc[mf][nf], af[mf], bh);
                    mma16816(acc[mf][nf], af[mf], bl);
                }
            }
#pragma unroll
            for (int mf = 0; mf < 4; mf++) lda(af[mf], sAl, wm + mf * 16, ks, lane);
#pragma unroll
            for (int nf = 0; nf < 4; nf++) {
                uint32_t bh[2];
                ldb(bh, sBh, wn + nf * 8, ks, lane);
#pragma unroll
                for (int mf = 0; mf < 4; mf++)
                    mma16816(acc[mf][nf], af[mf], bh);
            }
        }
        __syncthreads();
    }
}

// ---------------------------------------------------------------------------
// QKV GEMM + scale/RoPE epilogue -> pre-split bf16 q/k (head-major) and
// transposed hi/lo V ([bh][d][n]).
// ---------------------------------------------------------------------------
__global__ __launch_bounds__(256, 2) void qkv_mma_kernel(
    const float* __restrict__ X, const float* __restrict__ W)
{
    __shared__ __nv_bfloat16 sAh[128 * SSTR], sAl[128 * SSTR];
    __shared__ __nv_bfloat16 sBh[128 * SSTR], sBl[128 * SSTR];
    const int m0 = blockIdx.y * 128, c0 = blockIdx.x * 128;
    float acc[4][4][4];
    gemm_mma(X, W, CH, m0, c0, sAh, sAl, sBh, sBl, acc);

    const int tid = threadIdx.x, lane = tid & 31, wid = tid >> 5;
    const int wm = (wid >> 2) * 64, wn = (wid & 3) * 32;
    const int g = lane >> 2, t2 = (lane & 3) * 2;

    const int which = (c0 + wn) / CH;
    const float sc = (which == 0) ? 0.125f : 1.0f;

#pragma unroll
    for (int nf = 0; nf < 4; nf++) {
        const int col = c0 + wn + nf * 8 + t2;
        const int h   = (col % CH) >> 6;
        const int dd  = col & 63;                 // even
        const float inv = powf(10000.f, -((float)dd) / 64.f);
#pragma unroll
        for (int mf = 0; mf < 4; mf++) {
#pragma unroll
            for (int rr = 0; rr < 2; rr++) {
                const int m = m0 + wm + mf * 16 + g + rr * 8;
                const int b = m >> 11, n = m & 2047;
                const int bh = b * NH + h;
                float x0 = acc[mf][nf][rr * 2], x1 = acc[mf][nf][rr * 2 + 1];
                if (which == 2) {
                    __nv_bfloat16 h0 = __float2bfloat16_rn(x0);
                    __nv_bfloat16 h1 = __float2bfloat16_rn(x1);
                    size_t o0 = ((size_t)bh * HD + dd) * SEQ + n;
                    g_vth[o0]        = h0;
                    g_vth[o0 + SEQ]  = h1;
                    g_vtl[o0]        = __float2bfloat16_rn(x0 - __bfloat162float(h0));
                    g_vtl[o0 + SEQ]  = __float2bfloat16_rn(x1 - __bfloat162float(h1));
                } else {
                    float s, c;
                    sincosf((float)n * inv, &s, &c);
                    x0 *= sc; x1 *= sc;
                    float r0 = x0 * c - x1 * s, r1 = x1 * c + x0 * s;
                    uint32_t hi, lo;
                    splitpair(r0, r1, hi, lo);
                    size_t o = ((size_t)bh * SEQ + n) * HD + dd;
                    if (which == 0) {
                        *(uint32_t*)&g_qh[o] = hi; *(uint32_t*)&g_ql[o] = lo;
                    } else {
                        *(uint32_t*)&g_kh[o] = hi; *(uint32_t*)&g_kl[o] = lo;
                    }
                }
            }
        }
    }
}

// ---------------------------------------------------------------------------
// Flash attention, mma.sync. Block = (bh, 128 q rows). 8 warps x 16 rows.
// Q frags register-resident; K/V^T hi/lo staged in smem per 64-key tile;
// P frags built in-register from S C-frags (hi/lo split for PV too).
// ---------------------------------------------------------------------------
__global__ __launch_bounds__(256, 2) void flash_mma_kernel()
{
    __shared__ __nv_bfloat16 sKh[64 * KSTR], sKl[64 * KSTR];
    __shared__ __nv_bfloat16 sVh[64 * KSTR], sVl[64 * KSTR];

    const int tid = threadIdx.x, lane = tid & 31, wid = tid >> 5;
    const int g = lane >> 2, t2 = (lane & 3) * 2;
    const int bh = blockIdx.y;
    const int q0 = blockIdx.x * 128;
    const int qrow = q0 + wid * 16;

    // Q fragments (hi/lo), resident for whole kernel: [hl][ktile][reg]
    uint32_t qa[2][4][4];
#pragma unroll
    for (int hl = 0; hl < 2; hl++) {
        const __nv_bfloat16* Qp = hl ? g_ql : g_qh;
        const size_t r0 = ((size_t)bh * SEQ + qrow + g) * HD;
        const size_t r1 = ((size_t)bh * SEQ + qrow + g + 8) * HD;
#pragma unroll
        for (int t = 0; t < 4; t++) {
            qa[hl][t][0] = *(const uint32_t*)&Qp[r0 + t * 16 + t2];
            qa[hl][t][1] = *(const uint32_t*)&Qp[r1 + t * 16 + t2];
            qa[hl][t][2] = *(const uint32_t*)&Qp[r0 + t * 16 + t2 + 8];
            qa[hl][t][3] = *(const uint32_t*)&Qp[r1 + t * 16 + t2 + 8];
        }
    }

    float o[8][4];
#pragma unroll
    for (int nf = 0; nf < 8; nf++)
#pragma unroll
        for (int r = 0; r < 4; r++) o[nf][r] = 0.f;
    float mi[2] = {-1e30f, -1e30f}, li[2] = {0.f, 0.f};

    const int cr  = tid >> 2;            // 0..63 (key row / dim row)
    const int cc  = (tid & 3) * 16;      // 0,16,32,48

    for (int j0 = 0; j0 < SEQ; j0 += 64) {
        __syncthreads();
        {   // stage K (64 keys x 64 d) and V^T (64 d x 64 keys), hi+lo
            const size_t ko = ((size_t)bh * SEQ + j0 + cr) * HD + cc;
            const size_t vo = ((size_t)bh * HD + cr) * SEQ + j0 + cc;
            const uint4* p;
            p = (const uint4*)&g_kh[ko];
            *(uint4*)&sKh[cr * KSTR + cc] = p[0];
            *(uint4*)&sKh[cr * KSTR + cc + 8] = p[1];
            p = (const uint4*)&g_kl[ko];
            *(uint4*)&sKl[cr * KSTR + cc] = p[0];
            *(uint4*)&sKl[cr * KSTR + cc + 8] = p[1];
            p = (const uint4*)&g_vth[vo];
            *(uint4*)&sVh[cr * KSTR + cc] = p[0];
            *(uint4*)&sVh[cr * KSTR + cc + 8] = p[1];
            p = (const uint4*)&g_vtl[vo];
            *(uint4*)&sVl[cr * KSTR + cc] = p[0];
            *(uint4*)&sVl[cr * KSTR + cc + 8] = p[1];
        }
        __syncthreads();

        // S = Q.K^T : 8 nfrags (64 keys), hi/lo split
        float s[8][4];
#pragma unroll
        for (int nf = 0; nf < 8; nf++)
#pragma unroll
            for (int r = 0; r < 4; r++) s[nf][r] = 0.f;
#pragma unroll
        for (int t = 0; t < 4; t++) {
#pragma unroll
            for (int nf = 0; nf < 8; nf++) {
                uint32_t bh2[2], bl2[2];
                ldbf(bh2, sKh, nf * 8, t * 16, lane);
                ldbf(bl2, sKl, nf * 8, t * 16, lane);
                mma16816(s[nf], qa[0][t], bh2);
                mma16816(s[nf], qa[0][t], bl2);
                mma16816(s[nf], qa[1][t], bh2);
            }
        }

        // online softmax over the two rows (g, g+8) this thread owns
#pragma unroll
        for (int rr = 0; rr < 2; rr++) {
            float mx = -1e30f;
#pragma unroll
            for (int nf = 0; nf < 8; nf++)
                mx = fmaxf(mx, fmaxf(s[nf][rr * 2], s[nf][rr * 2 + 1]));
            mx = fmaxf(mx, __shfl_xor_sync(0xffffffffu, mx, 1));
            mx = fmaxf(mx, __shfl_xor_sync(0xffffffffu, mx, 2));
            float mnew = fmaxf(mi[rr], mx);
            float alpha = __expf(mi[rr] - mnew);
            mi[rr] = mnew;
            float sum = 0.f;
#pragma unroll
            for (int nf = 0; nf < 8; nf++) {
                float p0 = __expf(s[nf][rr * 2]     - mnew);
                float p1 = __expf(s[nf][rr * 2 + 1] - mnew);
                s[nf][rr * 2] = p0; s[nf][rr * 2 + 1] = p1;
                sum += p0 + p1;
            }
            sum += __shfl_xor_sync(0xffffffffu, sum, 1);
            sum += __shfl_xor_sync(0xffffffffu, sum, 2);
            li[rr] = li[rr] * alpha + sum;
#pragma unroll
            for (int nf = 0; nf < 8; nf++) {
                o[nf][rr * 2] *= alpha; o[nf][rr * 2 + 1] *= alpha;
            }
        }

        // O += P.V : P A-frags built in-register from S frags (hi/lo)
#pragma unroll
        for (int t = 0; t < 4; t++) {
            uint32_t ph[4], pl[4];
            splitpair(s[2*t][0],   s[2*t][1],   ph[0], pl[0]);
            splitpair(s[2*t][2],   s[2*t][3],   ph[1], pl[1]);
            splitpair(s[2*t+1][0], s[2*t+1][1], ph[2], pl[2]);
            splitpair(s[2*t+1][2], s[2*t+1][3], ph[3], pl[3]);
#pragma unroll
            for (int nf = 0; nf < 8; nf++) {
                uint32_t vh2[2], vl2[2];
                ldbf(vh2, sVh, nf * 8, t * 16, lane);
                ldbf(vl2, sVl, nf * 8, t * 16, lane);
                mma16816(o[nf], ph, vh2);
                mma16816(o[nf], ph, vl2);
                mma16816(o[nf], pl, vh2);
            }
        }
    }

    // epilogue: normalize and write ctx [B][N][C]
    const int b = bh / NH, h = bh % NH;
    const float inv0 = 1.f / li[0], inv1 = 1.f / li[1];
#pragma unroll
    for (int rr = 0; rr < 2; rr++) {
        const int n = qrow + g + rr * 8;
        const float inv = rr ? inv1 : inv0;
        float* base = &g_ctx[((size_t)b * SEQ + n) * CH + h * HD];
#pragma unroll
        for (int nf = 0; nf < 8; nf++)
            *(float2*)&base[nf * 8 + t2] =
                make_float2(o[nf][rr * 2] * inv, o[nf][rr * 2 + 1] * inv);
    }
}

// ---------------------------------------------------------------------------
// Output projection GEMM + bias.
// ---------------------------------------------------------------------------
__global__ __launch_bounds__(256, 2) void proj_mma_kernel(
    const float* __restrict__ W, const float* __restrict__ bias,
    float* __restrict__ out)
{
    __shared__ __nv_bfloat16 sAh[128 * SSTR], sAl[128 * SSTR];
    __shared__ __nv_bfloat16 sBh[128 * SSTR], sBl[128 * SSTR];
    const int m0 = blockIdx.y * 128, c0 = blockIdx.x * 128;
    float acc[4][4][4];
    gemm_mma(g_ctx, W, CH, m0, c0, sAh, sAl, sBh, sBl, acc);

    const int tid = threadIdx.x, lane = tid & 31, wid = tid >> 5;
    const int wm = (wid >> 2) * 64, wn = (wid & 3) * 32;
    const int g = lane >> 2, t2 = (lane & 3) * 2;

#pragma unroll
    for (int nf = 0; nf < 4; nf++) {
        const int col = c0 + wn + nf * 8 + t2;
        const float2 bv = *(const float2*)&bias[col];
#pragma unroll
        for (int mf = 0; mf < 4; mf++) {
#pragma unroll
            for (int rr = 0; rr < 2; rr++) {
                const int m = m0 + wm + mf * 16 + g + rr * 8;
                *(float2*)&out[(size_t)m * CH + col] =
                    make_float2(acc[mf][nf][rr * 2]     + bv.x,
                                acc[mf][nf][rr * 2 + 1] + bv.y);
            }
        }
    }
}

// ---------------------------------------------------------------------------
extern "C" void kernel_launch(void* const* d_in, const int* in_sizes, int n_in,
                              void* d_out, int out_size)
{
    const float* x      = (const float*)d_in[0];
    const float* w_qkv  = (const float*)d_in[1];
    const float* w_proj = (const float*)d_in[2];
    const float* b_proj = (const float*)d_in[3];
    float* out = (float*)d_out;

    dim3 g1(QKVN / 128, MROWS / 128);   // 18 x 32
    qkv_mma_kernel<<<g1, 256>>>(x, w_qkv);

    dim3 g2(SEQ / 128, BB * NH);        // 16 x 24
    flash_mma_kernel<<<g2, 256>>>();

    dim3 g3(CH / 128, MROWS / 128);     // 6 x 32
    proj_mma_kernel<<<g3, 256>>>(w_proj, b_proj, out);
}

// round 10
// speedup vs baseline: 2.6449x; 1.1138x over previous
#include <cuda_runtime.h>
#include <cuda_bf16.h>
#include <math.h>
#include <stdint.h>

#define BB   2
#define SEQ  2048
#define CH   768
#define NH   12
#define HD   64
#define MROWS (BB*SEQ)      // 4096
#define QKVN  (3*CH)        // 2304
#define SSTR  40            // gemm smem stride (bf16)
#define KSTR  72            // flash smem stride (bf16)

// ---- device global scratch (allocation-free rule) ----
__device__ __align__(16) __nv_bfloat16 g_xh[MROWS*CH],  g_xl[MROWS*CH];
__device__ __align__(16) __nv_bfloat16 g_wqh[QKVN*CH],  g_wql[QKVN*CH];
__device__ __align__(16) __nv_bfloat16 g_wph[CH*CH],    g_wpl[CH*CH];
__device__ __align__(16) __nv_bfloat16 g_qh[BB*NH*SEQ*HD], g_ql[BB*NH*SEQ*HD];
__device__ __align__(16) __nv_bfloat16 g_kh[BB*NH*SEQ*HD], g_kl[BB*NH*SEQ*HD];
__device__ __align__(16) __nv_bfloat16 g_vth[BB*NH*HD*SEQ], g_vtl[BB*NH*HD*SEQ];
__device__ __align__(16) __nv_bfloat16 g_ctxh[MROWS*CH], g_ctxl[MROWS*CH];

// ===========================================================================
// helpers
// ===========================================================================
__device__ __forceinline__ uint32_t smem_to_u32(const void* p) {
    uint32_t a;
    asm("{ .reg .u64 t; cvta.to.shared.u64 t, %1; cvt.u32.u64 %0, t; }"
        : "=r"(a) : "l"(p));
    return a;
}
#define CP16(s, g) \
    asm volatile("cp.async.cg.shared.global [%0], [%1], 16;" :: "r"(s), "l"(g))
#define CP_COMMIT() asm volatile("cp.async.commit_group;" ::: "memory")
#define CP_WAIT1()  asm volatile("cp.async.wait_group 1;" ::: "memory")
#define CP_WAIT0()  asm volatile("cp.async.wait_group 0;" ::: "memory")

__device__ __forceinline__ void mma16816(float* c, const uint32_t* a,
                                         const uint32_t* b) {
    asm volatile(
        "mma.sync.aligned.m16n8k16.row.col.f32.bf16.bf16.f32 "
        "{%0,%1,%2,%3}, {%4,%5,%6,%7}, {%8,%9}, {%0,%1,%2,%3};"
        : "+f"(c[0]), "+f"(c[1]), "+f"(c[2]), "+f"(c[3])
        : "r"(a[0]), "r"(a[1]), "r"(a[2]), "r"(a[3]), "r"(b[0]), "r"(b[1]));
}
__device__ __forceinline__ void lda(uint32_t a[4], const __nv_bfloat16* S,
                                    int row0, int k0, int lane) {
    const int g = lane >> 2, t2 = (lane & 3) * 2;
    a[0] = *(const uint32_t*)&S[(row0 + g)     * SSTR + k0 + t2];
    a[1] = *(const uint32_t*)&S[(row0 + g + 8) * SSTR + k0 + t2];
    a[2] = *(const uint32_t*)&S[(row0 + g)     * SSTR + k0 + t2 + 8];
    a[3] = *(const uint32_t*)&S[(row0 + g + 8) * SSTR + k0 + t2 + 8];
}
__device__ __forceinline__ void ldb(uint32_t b[2], const __nv_bfloat16* S,
                                    int col0, int k0, int lane) {
    const int g = lane >> 2, t2 = (lane & 3) * 2;
    b[0] = *(const uint32_t*)&S[(col0 + g) * SSTR + k0 + t2];
    b[1] = *(const uint32_t*)&S[(col0 + g) * SSTR + k0 + t2 + 8];
}
__device__ __forceinline__ void ldbf(uint32_t b[2], const __nv_bfloat16* S,
                                     int col0, int k0, int lane) {
    const int g = lane >> 2, t2 = (lane & 3) * 2;
    b[0] = *(const uint32_t*)&S[(col0 + g) * KSTR + k0 + t2];
    b[1] = *(const uint32_t*)&S[(col0 + g) * KSTR + k0 + t2 + 8];
}
__device__ __forceinline__ void splitpair(float x, float y,
                                          uint32_t& hi, uint32_t& lo) {
    __nv_bfloat16 hx = __float2bfloat16_rn(x), hy = __float2bfloat16_rn(y);
    __nv_bfloat162 h = __halves2bfloat162(hx, hy);
    hi = *(uint32_t*)&h;
    __nv_bfloat162 l = __floats2bfloat162_rn(x - __bfloat162float(hx),
                                             y - __bfloat162float(hy));
    lo = *(uint32_t*)&l;
}

// ---------------------------------------------------------------------------
// Pre-pass: split fp32 -> bf16 hi/lo (memory-bound, ~10us total)
// ---------------------------------------------------------------------------
__global__ void split_kernel(const float* __restrict__ src,
                             __nv_bfloat16* __restrict__ h,
                             __nv_bfloat16* __restrict__ l, int n4)
{
    int i = blockIdx.x * blockDim.x + threadIdx.x;
    if (i < n4) {
        float4 v = ((const float4*)src)[i];
        uint2 hi, lo;
        splitpair(v.x, v.y, hi.x, lo.x);
        splitpair(v.z, v.w, hi.y, lo.y);
        ((uint2*)h)[i] = hi;
        ((uint2*)l)[i] = lo;
    }
}

// ---------------------------------------------------------------------------
// GEMM core, bf16 pre-split inputs, cp.async double-buffered.
// D[128,128] = A[m0:+128,:K] . B[c0:+128,:K]^T  (hh + hl + lh, fp32 accum)
// Dynamic smem: 2 stages x 4 arrays x 128*SSTR bf16 = 81920 B.
// ---------------------------------------------------------------------------
#define ARRG  (128 * SSTR)            // elements per array
#define ARRGB (ARRG * 2)              // bytes
#define STAGEGB (4 * ARRGB)

__device__ __forceinline__ void gemm_issue(
    uint32_t sb, const __nv_bfloat16* Ah, const __nv_bfloat16* Al,
    const __nv_bfloat16* Bh, const __nv_bfloat16* Bl,
    int K, int m0, int c0, int k0, int tid)
{
#pragma unroll
    for (int t = 0; t < 2; t++) {
        int f = tid + t * 256, r = f >> 2, c = (f & 3) * 8;
        uint32_t off = (uint32_t)(r * (SSTR * 2) + c * 2);
        CP16(sb + off,             &Ah[(size_t)(m0 + r) * K + k0 + c]);
        CP16(sb + ARRGB + off,     &Al[(size_t)(m0 + r) * K + k0 + c]);
        CP16(sb + 2 * ARRGB + off, &Bh[(size_t)(c0 + r) * K + k0 + c]);
        CP16(sb + 3 * ARRGB + off, &Bl[(size_t)(c0 + r) * K + k0 + c]);
    }
    CP_COMMIT();
}

__device__ __forceinline__ void gemm_bf16(
    const __nv_bfloat16* __restrict__ Ah, const __nv_bfloat16* __restrict__ Al,
    const __nv_bfloat16* __restrict__ Bh, const __nv_bfloat16* __restrict__ Bl,
    int K, int m0, int c0, float acc[4][4][4])
{
    extern __shared__ __nv_bfloat16 smp[];
    const uint32_t sb0 = smem_to_u32(smp);
    const int tid = threadIdx.x, lane = tid & 31, wid = tid >> 5;
    const int wm = (wid >> 2) * 64, wn = (wid & 3) * 32;

#pragma unroll
    for (int i = 0; i < 4; i++)
#pragma unroll
        for (int j = 0; j < 4; j++)
#pragma unroll
            for (int r = 0; r < 4; r++) acc[i][j][r] = 0.f;

    const int nck = K / 32;
    gemm_issue(sb0, Ah, Al, Bh, Bl, K, m0, c0, 0, tid);

    for (int ck = 0; ck < nck; ck++) {
        if (ck + 1 < nck) {
            gemm_issue(sb0 + ((ck + 1) & 1) * STAGEGB, Ah, Al, Bh, Bl,
                       K, m0, c0, (ck + 1) * 32, tid);
            CP_WAIT1();
        } else {
            CP_WAIT0();
        }
        __syncthreads();

        const __nv_bfloat16* cAh = smp + ((ck & 1) * 4 + 0) * ARRG;
        const __nv_bfloat16* cAl = smp + ((ck & 1) * 4 + 1) * ARRG;
        const __nv_bfloat16* cBh = smp + ((ck & 1) * 4 + 2) * ARRG;
        const __nv_bfloat16* cBl = smp + ((ck & 1) * 4 + 3) * ARRG;

#pragma unroll
        for (int ks = 0; ks < 32; ks += 16) {
            uint32_t afh[4][4], afl[4][4];
#pragma unroll
            for (int mf = 0; mf < 4; mf++) {
                lda(afh[mf], cAh, wm + mf * 16, ks, lane);
                lda(afl[mf], cAl, wm + mf * 16, ks, lane);
            }
#pragma unroll
            for (int nf = 0; nf < 4; nf++) {
                uint32_t bh[2], bl[2];
                ldb(bh, cBh, wn + nf * 8, ks, lane);
                ldb(bl, cBl, wn + nf * 8, ks, lane);
#pragma unroll
                for (int mf = 0; mf < 4; mf++) {
                    mma16816(acc[mf][nf], afh[mf], bh);
                    mma16816(acc[mf][nf], afh[mf], bl);
                    mma16816(acc[mf][nf], afl[mf], bh);
                }
            }
        }
        __syncthreads();
    }
}

// ---------------------------------------------------------------------------
// QKV GEMM + scale/RoPE epilogue -> split q/k (head-major), transposed V.
// ---------------------------------------------------------------------------
__global__ __launch_bounds__(256, 2) void qkv_mma_kernel()
{
    const int m0 = blockIdx.y * 128, c0 = blockIdx.x * 128;
    float acc[4][4][4];
    gemm_bf16(g_xh, g_xl, g_wqh, g_wql, CH, m0, c0, acc);

    const int tid = threadIdx.x, lane = tid & 31, wid = tid >> 5;
    const int wm = (wid >> 2) * 64, wn = (wid & 3) * 32;
    const int g = lane >> 2, t2 = (lane & 3) * 2;

    const int which = (c0 + wn) / CH;
    const float sc = (which == 0) ? 0.125f : 1.0f;

#pragma unroll
    for (int nf = 0; nf < 4; nf++) {
        const int col = c0 + wn + nf * 8 + t2;
        const int h   = (col % CH) >> 6;
        const int dd  = col & 63;                 // even
        const float inv = powf(10000.f, -((float)dd) / 64.f);
#pragma unroll
        for (int mf = 0; mf < 4; mf++) {
#pragma unroll
            for (int rr = 0; rr < 2; rr++) {
                const int m = m0 + wm + mf * 16 + g + rr * 8;
                const int b = m >> 11, n = m & 2047;
                const int bh = b * NH + h;
                float x0 = acc[mf][nf][rr * 2], x1 = acc[mf][nf][rr * 2 + 1];
                if (which == 2) {
                    __nv_bfloat16 h0 = __float2bfloat16_rn(x0);
                    __nv_bfloat16 h1 = __float2bfloat16_rn(x1);
                    size_t o0 = ((size_t)bh * HD + dd) * SEQ + n;
                    g_vth[o0]       = h0;
                    g_vth[o0 + SEQ] = h1;
                    g_vtl[o0]       = __float2bfloat16_rn(x0 - __bfloat162float(h0));
                    g_vtl[o0 + SEQ] = __float2bfloat16_rn(x1 - __bfloat162float(h1));
                } else {
                    float s, c;
                    sincosf((float)n * inv, &s, &c);
                    x0 *= sc; x1 *= sc;
                    uint32_t hi, lo;
                    splitpair(x0 * c - x1 * s, x1 * c + x0 * s, hi, lo);
                    size_t o = ((size_t)bh * SEQ + n) * HD + dd;
                    if (which == 0) {
                        *(uint32_t*)&g_qh[o] = hi; *(uint32_t*)&g_ql[o] = lo;
                    } else {
                        *(uint32_t*)&g_kh[o] = hi; *(uint32_t*)&g_kl[o] = lo;
                    }
                }
            }
        }
    }
}

// ---------------------------------------------------------------------------
// Flash attention, mma.sync + cp.async double-buffered K/V^T tiles.
// Dynamic smem: 2 stages x 4 arrays x 64*KSTR bf16 = 73728 B.
// ---------------------------------------------------------------------------
#define ARRF  (64 * KSTR)
#define ARRFB (ARRF * 2)
#define STAGEFB (4 * ARRFB)

__device__ __forceinline__ void flash_issue(uint32_t sb, int bh, int j0, int tid)
{
#pragma unroll
    for (int t = 0; t < 2; t++) {
        int f = tid + t * 256, r = f >> 3, c8 = (f & 7) * 8;
        uint32_t off = (uint32_t)(r * (KSTR * 2) + c8 * 2);
        CP16(sb + off,             &g_kh[((size_t)bh * SEQ + j0 + r) * HD + c8]);
        CP16(sb + ARRFB + off,     &g_kl[((size_t)bh * SEQ + j0 + r) * HD + c8]);
        CP16(sb + 2 * ARRFB + off, &g_vth[((size_t)bh * HD + r) * SEQ + j0 + c8]);
        CP16(sb + 3 * ARRFB + off, &g_vtl[((size_t)bh * HD + r) * SEQ + j0 + c8]);
    }
    CP_COMMIT();
}

__global__ __launch_bounds__(256, 2) void flash_mma_kernel()
{
    extern __shared__ __nv_bfloat16 fsm[];
    const uint32_t sb0 = smem_to_u32(fsm);

    const int tid = threadIdx.x, lane = tid & 31, wid = tid >> 5;
    const int g = lane >> 2, t2 = (lane & 3) * 2;
    const int bh = blockIdx.y;
    const int q0 = blockIdx.x * 128;
    const int qrow = q0 + wid * 16;

    // Q fragments (hi/lo), register-resident
    uint32_t qa[2][4][4];
#pragma unroll
    for (int hl = 0; hl < 2; hl++) {
        const __nv_bfloat16* Qp = hl ? g_ql : g_qh;
        const size_t r0 = ((size_t)bh * SEQ + qrow + g) * HD;
        const size_t r1 = ((size_t)bh * SEQ + qrow + g + 8) * HD;
#pragma unroll
        for (int t = 0; t < 4; t++) {
            qa[hl][t][0] = *(const uint32_t*)&Qp[r0 + t * 16 + t2];
            qa[hl][t][1] = *(const uint32_t*)&Qp[r1 + t * 16 + t2];
            qa[hl][t][2] = *(const uint32_t*)&Qp[r0 + t * 16 + t2 + 8];
            qa[hl][t][3] = *(const uint32_t*)&Qp[r1 + t * 16 + t2 + 8];
        }
    }

    float o[8][4];
#pragma unroll
    for (int nf = 0; nf < 8; nf++)
#pragma unroll
        for (int r = 0; r < 4; r++) o[nf][r] = 0.f;
    float mi[2] = {-1e30f, -1e30f}, li[2] = {0.f, 0.f};

    flash_issue(sb0, bh, 0, tid);

    for (int jt = 0; jt < SEQ / 64; jt++) {
        if (jt + 1 < SEQ / 64) {
            flash_issue(sb0 + ((jt + 1) & 1) * STAGEFB, bh, (jt + 1) * 64, tid);
            CP_WAIT1();
        } else {
            CP_WAIT0();
        }
        __syncthreads();

        const __nv_bfloat16* cKh = fsm + ((jt & 1) * 4 + 0) * ARRF;
        const __nv_bfloat16* cKl = fsm + ((jt & 1) * 4 + 1) * ARRF;
        const __nv_bfloat16* cVh = fsm + ((jt & 1) * 4 + 2) * ARRF;
        const __nv_bfloat16* cVl = fsm + ((jt & 1) * 4 + 3) * ARRF;

        // S = Q.K^T
        float s[8][4];
#pragma unroll
        for (int nf = 0; nf < 8; nf++)
#pragma unroll
            for (int r = 0; r < 4; r++) s[nf][r] = 0.f;
#pragma unroll
        for (int t = 0; t < 4; t++) {
#pragma unroll
            for (int nf = 0; nf < 8; nf++) {
                uint32_t bh2[2], bl2[2];
                ldbf(bh2, cKh, nf * 8, t * 16, lane);
                ldbf(bl2, cKl, nf * 8, t * 16, lane);
                mma16816(s[nf], qa[0][t], bh2);
                mma16816(s[nf], qa[0][t], bl2);
                mma16816(s[nf], qa[1][t], bh2);
            }
        }

        // online softmax (rows g, g+8)
#pragma unroll
        for (int rr = 0; rr < 2; rr++) {
            float mx = -1e30f;
#pragma unroll
            for (int nf = 0; nf < 8; nf++)
                mx = fmaxf(mx, fmaxf(s[nf][rr * 2], s[nf][rr * 2 + 1]));
            mx = fmaxf(mx, __shfl_xor_sync(0xffffffffu, mx, 1));
            mx = fmaxf(mx, __shfl_xor_sync(0xffffffffu, mx, 2));
            float mnew = fmaxf(mi[rr], mx);
            float alpha = __expf(mi[rr] - mnew);
            mi[rr] = mnew;
            float sum = 0.f;
#pragma unroll
            for (int nf = 0; nf < 8; nf++) {
                float p0 = __expf(s[nf][rr * 2]     - mnew);
                float p1 = __expf(s[nf][rr * 2 + 1] - mnew);
                s[nf][rr * 2] = p0; s[nf][rr * 2 + 1] = p1;
                sum += p0 + p1;
            }
            sum += __shfl_xor_sync(0xffffffffu, sum, 1);
            sum += __shfl_xor_sync(0xffffffffu, sum, 2);
            li[rr] = li[rr] * alpha + sum;
#pragma unroll
            for (int nf = 0; nf < 8; nf++) {
                o[nf][rr * 2] *= alpha; o[nf][rr * 2 + 1] *= alpha;
            }
        }

        // O += P.V (P frags built in-register, hi/lo)
#pragma unroll
        for (int t = 0; t < 4; t++) {
            uint32_t ph[4], pl[4];
            splitpair(s[2*t][0],   s[2*t][1],   ph[0], pl[0]);
            splitpair(s[2*t][2],   s[2*t][3],   ph[1], pl[1]);
            splitpair(s[2*t+1][0], s[2*t+1][1], ph[2], pl[2]);
            splitpair(s[2*t+1][2], s[2*t+1][3], ph[3], pl[3]);
#pragma unroll
            for (int nf = 0; nf < 8; nf++) {
                uint32_t vh2[2], vl2[2];
                ldbf(vh2, cVh, nf * 8, t * 16, lane);
                ldbf(vl2, cVl, nf * 8, t * 16, lane);
                mma16816(o[nf], ph, vh2);
                mma16816(o[nf], ph, vl2);
                mma16816(o[nf], pl, vh2);
            }
        }
        __syncthreads();
    }

    // epilogue: normalize, split, write ctx hi/lo bf16 [B][N][C]
    const int b = bh / NH, h = bh % NH;
    const float inv0 = 1.f / li[0], inv1 = 1.f / li[1];
#pragma unroll
    for (int rr = 0; rr < 2; rr++) {
        const int n = qrow + g + rr * 8;
        const float inv = rr ? inv1 : inv0;
        const size_t base = ((size_t)b * SEQ + n) * CH + h * HD;
#pragma unroll
        for (int nf = 0; nf < 8; nf++) {
            uint32_t hi, lo;
            splitpair(o[nf][rr * 2] * inv, o[nf][rr * 2 + 1] * inv, hi, lo);
            *(uint32_t*)&g_ctxh[base + nf * 8 + t2] = hi;
            *(uint32_t*)&g_ctxl[base + nf * 8 + t2] = lo;
        }
    }
}

// ---------------------------------------------------------------------------
// Output projection GEMM + bias.
// ---------------------------------------------------------------------------
__global__ __launch_bounds__(256, 2) void proj_mma_kernel(
    const float* __restrict__ bias, float* __restrict__ out)
{
    const int m0 = blockIdx.y * 128, c0 = blockIdx.x * 128;
    float acc[4][4][4];
    gemm_bf16(g_ctxh, g_ctxl, g_wph, g_wpl, CH, m0, c0, acc);

    const int tid = threadIdx.x, lane = tid & 31, wid = tid >> 5;
    const int wm = (wid >> 2) * 64, wn = (wid & 3) * 32;
    const int g = lane >> 2, t2 = (lane & 3) * 2;

#pragma unroll
    for (int nf = 0; nf < 4; nf++) {
        const int col = c0 + wn + nf * 8 + t2;
        const float2 bv = *(const float2*)&bias[col];
#pragma unroll
        for (int mf = 0; mf < 4; mf++) {
#pragma unroll
            for (int rr = 0; rr < 2; rr++) {
                const int m = m0 + wm + mf * 16 + g + rr * 8;
                *(float2*)&out[(size_t)m * CH + col] =
                    make_float2(acc[mf][nf][rr * 2]     + bv.x,
                                acc[mf][nf][rr * 2 + 1] + bv.y);
            }
        }
    }
}

// ---------------------------------------------------------------------------
extern "C" void kernel_launch(void* const* d_in, const int* in_sizes, int n_in,
                              void* d_out, int out_size)
{
    const float* x      = (const float*)d_in[0];
    const float* w_qkv  = (const float*)d_in[1];
    const float* w_proj = (const float*)d_in[2];
    const float* b_proj = (const float*)d_in[3];
    float* out = (float*)d_out;

    const int gemm_smem  = 2 * STAGEGB;   // 81920
    const int flash_smem = 2 * STAGEFB;   // 73728
    cudaFuncSetAttribute(qkv_mma_kernel,
                         cudaFuncAttributeMaxDynamicSharedMemorySize, gemm_smem);
    cudaFuncSetAttribute(proj_mma_kernel,
                         cudaFuncAttributeMaxDynamicSharedMemorySize, gemm_smem);
    cudaFuncSetAttribute(flash_mma_kernel,
                         cudaFuncAttributeMaxDynamicSharedMemorySize, flash_smem);

    __nv_bfloat16 *p_xh, *p_xl, *p_wqh, *p_wql, *p_wph, *p_wpl;
    cudaGetSymbolAddress((void**)&p_xh,  g_xh);
    cudaGetSymbolAddress((void**)&p_xl,  g_xl);
    cudaGetSymbolAddress((void**)&p_wqh, g_wqh);
    cudaGetSymbolAddress((void**)&p_wql, g_wql);
    cudaGetSymbolAddress((void**)&p_wph, g_wph);
    cudaGetSymbolAddress((void**)&p_wpl, g_wpl);

    // pre-pass splits (memory-bound)
    split_kernel<<<(MROWS*CH/4 + 255)/256, 256>>>(x, p_xh, p_xl, MROWS*CH/4);
    split_kernel<<<(QKVN*CH/4  + 255)/256, 256>>>(w_qkv, p_wqh, p_wql, QKVN*CH/4);
    split_kernel<<<(CH*CH/4    + 255)/256, 256>>>(w_proj, p_wph, p_wpl, CH*CH/4);

    dim3 g1(QKVN / 128, MROWS / 128);   // 18 x 32
    qkv_mma_kernel<<<g1, 256, gemm_smem>>>();

    dim3 g2(SEQ / 128, BB * NH);        // 16 x 24
    flash_mma_kernel<<<g2, 256, flash_smem>>>();

    dim3 g3(CH / 128, MROWS / 128);     // 6 x 32
    proj_mma_kernel<<<g3, 256, gemm_smem>>>(b_proj, out);
}

// round 11
// speedup vs baseline: 2.8216x; 1.0668x over previous
#include <cuda_runtime.h>
#include <cuda_bf16.h>
#include <math.h>
#include <stdint.h>

#define BB   2
#define SEQ  2048
#define CH   768
#define NH   12
#define HD   64
#define MROWS (BB*SEQ)      // 4096
#define QKVN  (3*CH)        // 2304
#define SSTR  40            // gemm smem stride (bf16)
#define KSTR  72            // flash smem stride (bf16)

// ---- device global scratch ----
__device__ __align__(16) __nv_bfloat16 g_xh[MROWS*CH],  g_xl[MROWS*CH];
__device__ __align__(16) __nv_bfloat16 g_wqh[QKVN*CH],  g_wql[QKVN*CH];
__device__ __align__(16) __nv_bfloat16 g_wph[CH*CH],    g_wpl[CH*CH];
__device__ __align__(16) __nv_bfloat16 g_qh[BB*NH*SEQ*HD], g_ql[BB*NH*SEQ*HD];
__device__ __align__(16) __nv_bfloat16 g_kh[BB*NH*SEQ*HD], g_kl[BB*NH*SEQ*HD];
__device__ __align__(16) __nv_bfloat16 g_vth[BB*NH*HD*SEQ], g_vtl[BB*NH*HD*SEQ];
__device__ __align__(16) __nv_bfloat16 g_ctxh[MROWS*CH], g_ctxl[MROWS*CH];
__device__ __align__(16) float2 g_rope[SEQ * 32];   // [n][dd/2] = (cos, sin)

// ===========================================================================
// helpers
// ===========================================================================
__device__ __forceinline__ uint32_t smem_to_u32(const void* p) {
    uint32_t a;
    asm("{ .reg .u64 t; cvta.to.shared.u64 t, %1; cvt.u32.u64 %0, t; }"
        : "=r"(a) : "l"(p));
    return a;
}
#define CP16(s, g) \
    asm volatile("cp.async.cg.shared.global [%0], [%1], 16;" :: "r"(s), "l"(g))
#define CP_COMMIT() asm volatile("cp.async.commit_group;" ::: "memory")
#define CP_WAIT1()  asm volatile("cp.async.wait_group 1;" ::: "memory")
#define CP_WAIT0()  asm volatile("cp.async.wait_group 0;" ::: "memory")

__device__ __forceinline__ void mma16816(float* c, const uint32_t* a,
                                         const uint32_t* b) {
    asm volatile(
        "mma.sync.aligned.m16n8k16.row.col.f32.bf16.bf16.f32 "
        "{%0,%1,%2,%3}, {%4,%5,%6,%7}, {%8,%9}, {%0,%1,%2,%3};"
        : "+f"(c[0]), "+f"(c[1]), "+f"(c[2]), "+f"(c[3])
        : "r"(a[0]), "r"(a[1]), "r"(a[2]), "r"(a[3]), "r"(b[0]), "r"(b[1]));
}
__device__ __forceinline__ void ldsm4(uint32_t r[4], uint32_t a) {
    asm volatile("ldmatrix.sync.aligned.m8n8.x4.shared.b16 {%0,%1,%2,%3}, [%4];"
        : "=r"(r[0]), "=r"(r[1]), "=r"(r[2]), "=r"(r[3]) : "r"(a));
}
__device__ __forceinline__ void splitpair(float x, float y,
                                          uint32_t& hi, uint32_t& lo) {
    __nv_bfloat16 hx = __float2bfloat16_rn(x), hy = __float2bfloat16_rn(y);
    __nv_bfloat162 h = __halves2bfloat162(hx, hy);
    hi = *(uint32_t*)&h;
    __nv_bfloat162 l = __floats2bfloat162_rn(x - __bfloat162float(hx),
                                             y - __bfloat162float(hy));
    lo = *(uint32_t*)&l;
}

// per-lane byte offsets for ldmatrix.x4 fragment loads
// A-frag (row-major, rows m): matrices {(g,k0),(g+8,k0),(g,k0+8),(g+8,k0+8)}
__device__ __forceinline__ uint32_t aoff_lane(int lane, int stride) {
    return (uint32_t)((((lane & 7) + ((lane >> 3) & 1) * 8) * stride +
                       ((lane >> 4) << 3)) * 2);
}
// B-frag pair (n-major rows): matrices {(nA,k0),(nA,k0+8),(nB,k0),(nB,k0+8)}
__device__ __forceinline__ uint32_t boff_lane(int lane, int stride) {
    return (uint32_t)((((lane & 7) + ((lane >> 4) << 3)) * stride +
                       ((lane >> 3) & 1) * 8) * 2);
}

// ---------------------------------------------------------------------------
// Pre-passes
// ---------------------------------------------------------------------------
__global__ void split_kernel(const float* __restrict__ src,
                             __nv_bfloat16* __restrict__ h,
                             __nv_bfloat16* __restrict__ l, int n4)
{
    int i = blockIdx.x * blockDim.x + threadIdx.x;
    if (i < n4) {
        float4 v = ((const float4*)src)[i];
        uint2 hi, lo;
        splitpair(v.x, v.y, hi.x, lo.x);
        splitpair(v.z, v.w, hi.y, lo.y);
        ((uint2*)h)[i] = hi;
        ((uint2*)l)[i] = lo;
    }
}
__global__ void rope_kernel()
{
    int i = blockIdx.x * blockDim.x + threadIdx.x;   // i < SEQ*32
    if (i < SEQ * 32) {
        int n = i >> 5, dd2 = i & 31;
        float freq = powf(10000.f, -((float)(2 * dd2)) / 64.f);
        float s, c;
        sincosf((float)n * freq, &s, &c);
        g_rope[i] = make_float2(c, s);
    }
}

// ---------------------------------------------------------------------------
// GEMM core (bf16 pre-split, cp.async double-buffered, LDSM fragments)
// ---------------------------------------------------------------------------
#define ARRG  (128 * SSTR)
#define ARRGB (ARRG * 2)
#define STAGEGB (4 * ARRGB)

__device__ __forceinline__ void gemm_issue(
    uint32_t sb, const __nv_bfloat16* Ah, const __nv_bfloat16* Al,
    const __nv_bfloat16* Bh, const __nv_bfloat16* Bl,
    int K, int m0, int c0, int k0, int tid)
{
#pragma unroll
    for (int t = 0; t < 2; t++) {
        int f = tid + t * 256, r = f >> 2, c = (f & 3) * 8;
        uint32_t off = (uint32_t)(r * (SSTR * 2) + c * 2);
        CP16(sb + off,             &Ah[(size_t)(m0 + r) * K + k0 + c]);
        CP16(sb + ARRGB + off,     &Al[(size_t)(m0 + r) * K + k0 + c]);
        CP16(sb + 2 * ARRGB + off, &Bh[(size_t)(c0 + r) * K + k0 + c]);
        CP16(sb + 3 * ARRGB + off, &Bl[(size_t)(c0 + r) * K + k0 + c]);
    }
    CP_COMMIT();
}

__device__ __forceinline__ void gemm_bf16(
    const __nv_bfloat16* __restrict__ Ah, const __nv_bfloat16* __restrict__ Al,
    const __nv_bfloat16* __restrict__ Bh, const __nv_bfloat16* __restrict__ Bl,
    int K, int m0, int c0, float acc[4][4][4])
{
    extern __shared__ __nv_bfloat16 smp[];
    const uint32_t sb0 = smem_to_u32(smp);
    const int tid = threadIdx.x, lane = tid & 31, wid = tid >> 5;
    const int wm = (wid >> 2) * 64, wn = (wid & 3) * 32;
    const uint32_t ao = aoff_lane(lane, SSTR);
    const uint32_t bo = boff_lane(lane, SSTR);

#pragma unroll
    for (int i = 0; i < 4; i++)
#pragma unroll
        for (int j = 0; j < 4; j++)
#pragma unroll
            for (int r = 0; r < 4; r++) acc[i][j][r] = 0.f;

    const int nck = K / 32;
    gemm_issue(sb0, Ah, Al, Bh, Bl, K, m0, c0, 0, tid);

    for (int ck = 0; ck < nck; ck++) {
        if (ck + 1 < nck) {
            gemm_issue(sb0 + ((ck + 1) & 1) * STAGEGB, Ah, Al, Bh, Bl,
                       K, m0, c0, (ck + 1) * 32, tid);
            CP_WAIT1();
        } else {
            CP_WAIT0();
        }
        __syncthreads();

        const uint32_t st = sb0 + (ck & 1) * STAGEGB;
        const uint32_t cAh = st, cAl = st + ARRGB;
        const uint32_t cBh = st + 2 * ARRGB, cBl = st + 3 * ARRGB;

#pragma unroll
        for (int ks = 0; ks < 32; ks += 16) {
            uint32_t ah[4][4], al[4][4];
#pragma unroll
            for (int mf = 0; mf < 4; mf++) {
                uint32_t ra = (uint32_t)(((wm + mf * 16) * SSTR + ks) * 2) + ao;
                ldsm4(ah[mf], cAh + ra);
                ldsm4(al[mf], cAl + ra);
            }
#pragma unroll
            for (int p = 0; p < 2; p++) {
                uint32_t bh4[4], bl4[4];
                uint32_t rb = (uint32_t)(((wn + p * 16) * SSTR + ks) * 2) + bo;
                ldsm4(bh4, cBh + rb);
                ldsm4(bl4, cBl + rb);
#pragma unroll
                for (int sub = 0; sub < 2; sub++) {
                    const int nf = p * 2 + sub;
#pragma unroll
                    for (int mf = 0; mf < 4; mf++) {
                        mma16816(acc[mf][nf], ah[mf], &bh4[sub * 2]);
                        mma16816(acc[mf][nf], ah[mf], &bl4[sub * 2]);
                        mma16816(acc[mf][nf], al[mf], &bh4[sub * 2]);
                    }
                }
            }
        }
        __syncthreads();
    }
}

// ---------------------------------------------------------------------------
// QKV GEMM + scale/RoPE(table) epilogue -> split q/k (head-major), V^T.
// ---------------------------------------------------------------------------
__global__ __launch_bounds__(256, 2) void qkv_mma_kernel()
{
    const int m0 = blockIdx.y * 128, c0 = blockIdx.x * 128;
    float acc[4][4][4];
    gemm_bf16(g_xh, g_xl, g_wqh, g_wql, CH, m0, c0, acc);

    const int tid = threadIdx.x, lane = tid & 31, wid = tid >> 5;
    const int wm = (wid >> 2) * 64, wn = (wid & 3) * 32;
    const int g = lane >> 2, t2 = (lane & 3) * 2;

    const int which = (c0 + wn) / CH;
    const float sc = (which == 0) ? 0.125f : 1.0f;

#pragma unroll
    for (int nf = 0; nf < 4; nf++) {
        const int col = c0 + wn + nf * 8 + t2;
        const int h   = (col % CH) >> 6;
        const int dd  = col & 63;                 // even
#pragma unroll
        for (int mf = 0; mf < 4; mf++) {
#pragma unroll
            for (int rr = 0; rr < 2; rr++) {
                const int m = m0 + wm + mf * 16 + g + rr * 8;
                const int b = m >> 11, n = m & 2047;
                const int bh = b * NH + h;
                float x0 = acc[mf][nf][rr * 2], x1 = acc[mf][nf][rr * 2 + 1];
                if (which == 2) {
                    __nv_bfloat16 h0 = __float2bfloat16_rn(x0);
                    __nv_bfloat16 h1 = __float2bfloat16_rn(x1);
                    size_t o0 = ((size_t)bh * HD + dd) * SEQ + n;
                    g_vth[o0]       = h0;
                    g_vth[o0 + SEQ] = h1;
                    g_vtl[o0]       = __float2bfloat16_rn(x0 - __bfloat162float(h0));
                    g_vtl[o0 + SEQ] = __float2bfloat16_rn(x1 - __bfloat162float(h1));
                } else {
                    const float2 cs = g_rope[(n << 5) + (dd >> 1)];
                    x0 *= sc; x1 *= sc;
                    uint32_t hi, lo;
                    splitpair(x0 * cs.x - x1 * cs.y, x1 * cs.x + x0 * cs.y, hi, lo);
                    size_t o = ((size_t)bh * SEQ + n) * HD + dd;
                    if (which == 0) {
                        *(uint32_t*)&g_qh[o] = hi; *(uint32_t*)&g_ql[o] = lo;
                    } else {
                        *(uint32_t*)&g_kh[o] = hi; *(uint32_t*)&g_kl[o] = lo;
                    }
                }
            }
        }
    }
}

// ---------------------------------------------------------------------------
// Flash attention, mma.sync + cp.async + LDSM fragments.
// ---------------------------------------------------------------------------
#define ARRF  (64 * KSTR)
#define ARRFB (ARRF * 2)
#define STAGEFB (4 * ARRFB)

__device__ __forceinline__ void flash_issue(uint32_t sb, int bh, int j0, int tid)
{
#pragma unroll
    for (int t = 0; t < 2; t++) {
        int f = tid + t * 256, r = f >> 3, c8 = (f & 7) * 8;
        uint32_t off = (uint32_t)(r * (KSTR * 2) + c8 * 2);
        CP16(sb + off,             &g_kh[((size_t)bh * SEQ + j0 + r) * HD + c8]);
        CP16(sb + ARRFB + off,     &g_kl[((size_t)bh * SEQ + j0 + r) * HD + c8]);
        CP16(sb + 2 * ARRFB + off, &g_vth[((size_t)bh * HD + r) * SEQ + j0 + c8]);
        CP16(sb + 3 * ARRFB + off, &g_vtl[((size_t)bh * HD + r) * SEQ + j0 + c8]);
    }
    CP_COMMIT();
}

__global__ __launch_bounds__(256, 2) void flash_mma_kernel()
{
    extern __shared__ __nv_bfloat16 fsm[];
    const uint32_t sb0 = smem_to_u32(fsm);

    const int tid = threadIdx.x, lane = tid & 31, wid = tid >> 5;
    const int g = lane >> 2, t2 = (lane & 3) * 2;
    const int bh = blockIdx.y;
    const int q0 = blockIdx.x * 128;
    const int qrow = q0 + wid * 16;
    const uint32_t bo = boff_lane(lane, KSTR);

    // Q fragments (hi/lo), register-resident
    uint32_t qa[2][4][4];
#pragma unroll
    for (int hl = 0; hl < 2; hl++) {
        const __nv_bfloat16* Qp = hl ? g_ql : g_qh;
        const size_t r0 = ((size_t)bh * SEQ + qrow + g) * HD;
        const size_t r1 = ((size_t)bh * SEQ + qrow + g + 8) * HD;
#pragma unroll
        for (int t = 0; t < 4; t++) {
            qa[hl][t][0] = *(const uint32_t*)&Qp[r0 + t * 16 + t2];
            qa[hl][t][1] = *(const uint32_t*)&Qp[r1 + t * 16 + t2];
            qa[hl][t][2] = *(const uint32_t*)&Qp[r0 + t * 16 + t2 + 8];
            qa[hl][t][3] = *(const uint32_t*)&Qp[r1 + t * 16 + t2 + 8];
        }
    }

    float o[8][4];
#pragma unroll
    for (int nf = 0; nf < 8; nf++)
#pragma unroll
        for (int r = 0; r < 4; r++) o[nf][r] = 0.f;
    float mi[2] = {-1e30f, -1e30f}, li[2] = {0.f, 0.f};

    flash_issue(sb0, bh, 0, tid);

    for (int jt = 0; jt < SEQ / 64; jt++) {
        if (jt + 1 < SEQ / 64) {
            flash_issue(sb0 + ((jt + 1) & 1) * STAGEFB, bh, (jt + 1) * 64, tid);
            CP_WAIT1();
        } else {
            CP_WAIT0();
        }
        __syncthreads();

        const uint32_t st = sb0 + (jt & 1) * STAGEFB;
        const uint32_t cKh = st, cKl = st + ARRFB;
        const uint32_t cVh = st + 2 * ARRFB, cVl = st + 3 * ARRFB;

        // S = Q.K^T
        float s[8][4];
#pragma unroll
        for (int nf = 0; nf < 8; nf++)
#pragma unroll
            for (int r = 0; r < 4; r++) s[nf][r] = 0.f;
#pragma unroll
        for (int t = 0; t < 4; t++) {
#pragma unroll
            for (int p = 0; p < 4; p++) {
                uint32_t kh4[4], kl4[4];
                uint32_t rb = (uint32_t)((p * 16 * KSTR + t * 16) * 2) + bo;
                ldsm4(kh4, cKh + rb);
                ldsm4(kl4, cKl + rb);
#pragma unroll
                for (int sub = 0; sub < 2; sub++) {
                    const int nf = p * 2 + sub;
                    mma16816(s[nf], qa[0][t], &kh4[sub * 2]);
                    mma16816(s[nf], qa[0][t], &kl4[sub * 2]);
                    mma16816(s[nf], qa[1][t], &kh4[sub * 2]);
                }
            }
        }

        // online softmax (rows g, g+8)
#pragma unroll
        for (int rr = 0; rr < 2; rr++) {
            float mx = -1e30f;
#pragma unroll
            for (int nf = 0; nf < 8; nf++)
                mx = fmaxf(mx, fmaxf(s[nf][rr * 2], s[nf][rr * 2 + 1]));
            mx = fmaxf(mx, __shfl_xor_sync(0xffffffffu, mx, 1));
            mx = fmaxf(mx, __shfl_xor_sync(0xffffffffu, mx, 2));
            float mnew = fmaxf(mi[rr], mx);
            float alpha = __expf(mi[rr] - mnew);
            mi[rr] = mnew;
            float sum = 0.f;
#pragma unroll
            for (int nf = 0; nf < 8; nf++) {
                float p0 = __expf(s[nf][rr * 2]     - mnew);
                float p1 = __expf(s[nf][rr * 2 + 1] - mnew);
                s[nf][rr * 2] = p0; s[nf][rr * 2 + 1] = p1;
                sum += p0 + p1;
            }
            sum += __shfl_xor_sync(0xffffffffu, sum, 1);
            sum += __shfl_xor_sync(0xffffffffu, sum, 2);
            li[rr] = li[rr] * alpha + sum;
#pragma unroll
            for (int nf = 0; nf < 8; nf++) {
                o[nf][rr * 2] *= alpha; o[nf][rr * 2 + 1] *= alpha;
            }
        }

        // O += P.V
#pragma unroll
        for (int t = 0; t < 4; t++) {
            uint32_t ph[4], pl[4];
            splitpair(s[2*t][0],   s[2*t][1],   ph[0], pl[0]);
            splitpair(s[2*t][2],   s[2*t][3],   ph[1], pl[1]);
            splitpair(s[2*t+1][0], s[2*t+1][1], ph[2], pl[2]);
            splitpair(s[2*t+1][2], s[2*t+1][3], ph[3], pl[3]);
#pragma unroll
            for (int p = 0; p < 4; p++) {
                uint32_t vh4[4], vl4[4];
                uint32_t rb = (uint32_t)((p * 16 * KSTR + t * 16) * 2) + bo;
                ldsm4(vh4, cVh + rb);
                ldsm4(vl4, cVl + rb);
#pragma unroll
                for (int sub = 0; sub < 2; sub++) {
                    const int nf = p * 2 + sub;
                    mma16816(o[nf], ph, &vh4[sub * 2]);
                    mma16816(o[nf], ph, &vl4[sub * 2]);
                    mma16816(o[nf], pl, &vh4[sub * 2]);
                }
            }
        }
        __syncthreads();
    }

    // epilogue: normalize, split, write ctx hi/lo bf16 [B][N][C]
    const int b = bh / NH, h = bh % NH;
    const float inv0 = 1.f / li[0], inv1 = 1.f / li[1];
#pragma unroll
    for (int rr = 0; rr < 2; rr++) {
        const int n = qrow + g + rr * 8;
        const float inv = rr ? inv1 : inv0;
        const size_t base = ((size_t)b * SEQ + n) * CH + h * HD;
#pragma unroll
        for (int nf = 0; nf < 8; nf++) {
            uint32_t hi, lo;
            splitpair(o[nf][rr * 2] * inv, o[nf][rr * 2 + 1] * inv, hi, lo);
            *(uint32_t*)&g_ctxh[base + nf * 8 + t2] = hi;
            *(uint32_t*)&g_ctxl[base + nf * 8 + t2] = lo;
        }
    }
}

// ---------------------------------------------------------------------------
// Output projection GEMM + bias.
// ---------------------------------------------------------------------------
__global__ __launch_bounds__(256, 2) void proj_mma_kernel(
    const float* __restrict__ bias, float* __restrict__ out)
{
    const int m0 = blockIdx.y * 128, c0 = blockIdx.x * 128;
    float acc[4][4][4];
    gemm_bf16(g_ctxh, g_ctxl, g_wph, g_wpl, CH, m0, c0, acc);

    const int tid = threadIdx.x, lane = tid & 31, wid = tid >> 5;
    const int wm = (wid >> 2) * 64, wn = (wid & 3) * 32;
    const int g = lane >> 2, t2 = (lane & 3) * 2;

#pragma unroll
    for (int nf = 0; nf < 4; nf++) {
        const int col = c0 + wn + nf * 8 + t2;
        const float2 bv = *(const float2*)&bias[col];
#pragma unroll
        for (int mf = 0; mf < 4; mf++) {
#pragma unroll
            for (int rr = 0; rr < 2; rr++) {
                const int m = m0 + wm + mf * 16 + g + rr * 8;
                *(float2*)&out[(size_t)m * CH + col] =
                    make_float2(acc[mf][nf][rr * 2]     + bv.x,
                                acc[mf][nf][rr * 2 + 1] + bv.y);
            }
        }
    }
}

// ---------------------------------------------------------------------------
extern "C" void kernel_launch(void* const* d_in, const int* in_sizes, int n_in,
                              void* d_out, int out_size)
{
    const float* x      = (const float*)d_in[0];
    const float* w_qkv  = (const float*)d_in[1];
    const float* w_proj = (const float*)d_in[2];
    const float* b_proj = (const float*)d_in[3];
    float* out = (float*)d_out;

    const int gemm_smem  = 2 * STAGEGB;   // 81920
    const int flash_smem = 2 * STAGEFB;   // 73728
    cudaFuncSetAttribute(qkv_mma_kernel,
                         cudaFuncAttributeMaxDynamicSharedMemorySize, gemm_smem);
    cudaFuncSetAttribute(proj_mma_kernel,
                         cudaFuncAttributeMaxDynamicSharedMemorySize, gemm_smem);
    cudaFuncSetAttribute(flash_mma_kernel,
                         cudaFuncAttributeMaxDynamicSharedMemorySize, flash_smem);

    __nv_bfloat16 *p_xh, *p_xl, *p_wqh, *p_wql, *p_wph, *p_wpl;
    cudaGetSymbolAddress((void**)&p_xh,  g_xh);
    cudaGetSymbolAddress((void**)&p_xl,  g_xl);
    cudaGetSymbolAddress((void**)&p_wqh, g_wqh);
    cudaGetSymbolAddress((void**)&p_wql, g_wql);
    cudaGetSymbolAddress((void**)&p_wph, g_wph);
    cudaGetSymbolAddress((void**)&p_wpl, g_wpl);

    // pre-passes
    split_kernel<<<(MROWS*CH/4 + 255)/256, 256>>>(x, p_xh, p_xl, MROWS*CH/4);
    split_kernel<<<(QKVN*CH/4  + 255)/256, 256>>>(w_qkv, p_wqh, p_wql, QKVN*CH/4);
    split_kernel<<<(CH*CH/4    + 255)/256, 256>>>(w_proj, p_wph, p_wpl, CH*CH/4);
    rope_kernel<<<(SEQ*32 + 255)/256, 256>>>();

    dim3 g1(QKVN / 128, MROWS / 128);   // 18 x 32
    qkv_mma_kernel<<<g1, 256, gemm_smem>>>();

    dim3 g2(SEQ / 128, BB * NH);        // 16 x 24
    flash_mma_kernel<<<g2, 256, flash_smem>>>();

    dim3 g3(CH / 128, MROWS / 128);     // 6 x 32
    proj_mma_kernel<<<g3, 256, gemm_smem>>>(b_proj, out);
}